// round 7
// baseline (speedup 1.0000x reference)
#include <cuda_runtime.h>
#include <cstdint>

// ---------------------------------------------------------------------------
// FeaStEncoderBlock, input-space aggregation + bf16-split tensor-core GEMM.
// Round 7: weights pre-split to bf16 hi/lo pair-words ONCE (g_wbh/g_wbl);
// GEMM tile 64x256 (grid = 313 blocks -> single wave at occ 2).
// ---------------------------------------------------------------------------

#define MAXN 20000
#define MAXE 320000

__device__ __align__(16) float    g_y[(size_t)MAXN * 1024];   // z buffer
__device__ __align__(16) float    g_h[(size_t)MAXN * 256];    // hidden h
__device__ __align__(16) uint32_t g_wbh[512 * 256];           // W hi bf16-pair words
__device__ __align__(16) uint32_t g_wbl[512 * 256];           // W lo bf16-pair words
__device__ __align__(16) float    g_ea[MAXN * 4];
__device__ __align__(16) float    g_eb[MAXN * 4];
__device__ int g_deg[MAXN];
__device__ int g_cur[MAXN];
__device__ int g_offs[MAXN + 1];
__device__ int g_srcs[MAXN + MAXE];

// ---------------------------------------------------------------- CSR build
__global__ void k_init(int n) {
    int i = blockIdx.x * blockDim.x + threadIdx.x;
    if (i < n) { g_deg[i] = 1; g_cur[i] = 0; }
}

__global__ void k_hist(const int* __restrict__ ei, int E, int n) {
    int t = blockIdx.x * blockDim.x + threadIdx.x;
    if (t < E) {
        int d = ei[E + t];
        if (d >= 0 && d < n) atomicAdd(&g_deg[d], 1);
    }
}

__global__ void k_scan(int n) {
    __shared__ int sh[1024];
    __shared__ int carry;
    if (threadIdx.x == 0) carry = 0;
    __syncthreads();
    int nchunks = (n + 1023) / 1024;
    for (int chunk = 0; chunk < nchunks; ++chunk) {
        int i = chunk * 1024 + threadIdx.x;
        int v = (i < n) ? g_deg[i] : 0;
        sh[threadIdx.x] = v;
        __syncthreads();
        #pragma unroll
        for (int off = 1; off < 1024; off <<= 1) {
            int t = (threadIdx.x >= off) ? sh[threadIdx.x - off] : 0;
            __syncthreads();
            sh[threadIdx.x] += t;
            __syncthreads();
        }
        int incl = sh[threadIdx.x] + carry;
        if (i < n) g_offs[i + 1] = incl;
        __syncthreads();
        if (threadIdx.x == 1023) carry = incl;
        __syncthreads();
    }
    if (threadIdx.x == 0) g_offs[0] = 0;
}

__global__ void k_fill(const int* __restrict__ ei, int E, int n) {
    int t = blockIdx.x * blockDim.x + threadIdx.x;
    if (t >= E + n) return;
    int s, d;
    if (t < E) { s = ei[t]; d = ei[E + t]; }
    else       { s = d = t - E; }
    if (s < 0 || s >= n || d < 0 || d >= n) return;
    int pos = g_offs[d] + atomicAdd(&g_cur[d], 1);
    g_srcs[pos] = s;
}

// -------------------------------------------- per-node attention projections
__global__ void k_nodep(const float* __restrict__ x_ext, int x_sel,
                        const float* __restrict__ u,
                        const float* __restrict__ c, int K, int n) {
    int warp = (blockIdx.x * blockDim.x + threadIdx.x) >> 5;
    int lane = threadIdx.x & 31;
    if (warp >= n) return;
    const float* x = x_sel ? g_h : x_ext;
    const float* xr = x + (size_t)warp * K;
    float a0 = 0.f, a1 = 0.f, a2 = 0.f, a3 = 0.f;
    for (int k = lane; k < K; k += 32) {
        float xv = xr[k];
        float4 uv = ((const float4*)u)[k];
        a0 += xv * uv.x; a1 += xv * uv.y; a2 += xv * uv.z; a3 += xv * uv.w;
    }
    #pragma unroll
    for (int off = 16; off; off >>= 1) {
        a0 += __shfl_down_sync(0xffffffffu, a0, off);
        a1 += __shfl_down_sync(0xffffffffu, a1, off);
        a2 += __shfl_down_sync(0xffffffffu, a2, off);
        a3 += __shfl_down_sync(0xffffffffu, a3, off);
    }
    if (lane == 0) {
        float4 ea, eb;
        ea.x = expf(a0 + c[0]); ea.y = expf(a1 + c[1]);
        ea.z = expf(a2 + c[2]); ea.w = expf(a3 + c[3]);
        eb.x = expf(-a0); eb.y = expf(-a1); eb.z = expf(-a2); eb.w = expf(-a3);
        ((float4*)g_ea)[warp] = ea;
        ((float4*)g_eb)[warp] = eb;
    }
}

// ------------------------------------------------ input-space aggregation
__device__ __forceinline__ float4 fma4(float4 a, float s, float4 v) {
    a.x += s * v.x; a.y += s * v.y; a.z += s * v.z; a.w += s * v.w; return a;
}

template<int IN, int ZC>
__global__ void k_agg_in(const float* __restrict__ x_ext, int x_sel, int n) {
    constexpr int V = IN / 128;
    int warp = (blockIdx.x * blockDim.x + threadIdx.x) >> 5;
    int lane = threadIdx.x & 31;
    if (warp >= n) return;
    const float* x = x_sel ? g_h : x_ext;
    int i  = warp;
    int s0 = g_offs[i], s1 = g_offs[i + 1];
    float4 ebi = ((const float4*)g_eb)[i];

    float4 acc[4][V];
    #pragma unroll
    for (int h = 0; h < 4; h++)
        #pragma unroll
        for (int v = 0; v < V; v++) acc[h][v] = make_float4(0.f, 0.f, 0.f, 0.f);

    for (int e = s0; e < s1; ++e) {
        int j = g_srcs[e];
        float4 a = ((const float4*)g_ea)[j];
        float q0 = a.x * ebi.x, q1 = a.y * ebi.y, q2 = a.z * ebi.z, q3 = a.w * ebi.w;
        float rz = 1.0f / (q0 + q1 + q2 + q3);
        q0 *= rz; q1 *= rz; q2 *= rz; q3 *= rz;
        const float4* xj = (const float4*)(x + (size_t)j * IN);
        #pragma unroll
        for (int v = 0; v < V; v++) {
            float4 xv = xj[lane + 32 * v];
            acc[0][v] = fma4(acc[0][v], q0, xv);
            acc[1][v] = fma4(acc[1][v], q1, xv);
            acc[2][v] = fma4(acc[2][v], q2, xv);
            acc[3][v] = fma4(acc[3][v], q3, xv);
        }
    }
    float inv = 1.0f / (float)(s1 - s0 > 0 ? s1 - s0 : 1);
    float4* z = (float4*)(g_y + (size_t)i * ZC);
    #pragma unroll
    for (int h = 0; h < 4; h++)
        #pragma unroll
        for (int v = 0; v < V; v++) {
            float4 r = acc[h][v];
            r.x *= inv; r.y *= inv; r.z *= inv; r.w *= inv;
            z[h * (IN / 4) + lane + 32 * v] = r;
        }
    if (ZC > 4 * IN) {
        const float4* xi = (const float4*)(x + (size_t)i * IN);
        #pragma unroll
        for (int v = 0; v < V; v++)
            z[IN + lane + 32 * v] = xi[lane + 32 * v];
    }
}

// -------------------------------------------------------- bf16 split utils
__device__ __forceinline__ uint32_t pack_bf16(float lo_elem, float hi_elem) {
    uint32_t r;
    asm("cvt.rn.bf16x2.f32 %0, %1, %2;" : "=r"(r) : "f"(hi_elem), "f"(lo_elem));
    return r;
}
// word packs (f0 -> lower 16 = k even, f1 -> upper 16 = k odd)
__device__ __forceinline__ void split_pair(float f0, float f1,
                                           uint32_t& hw, uint32_t& lw) {
    hw = pack_bf16(f0, f1);
    float h0 = __uint_as_float(hw << 16);
    float h1 = __uint_as_float(hw & 0xffff0000u);
    lw = pack_bf16(f0 - h0, f1 - h1);
}

// ------------------------------- stacked weight builders + bf16 pre-split
// Wstack[k, d]: k<4*in -> W[k%in, (k/in)*256 + d]; k>=4*in -> skipW[k-4in, d]
// Pair-word [p][d] packs rows (2p, 2p+1).
__global__ void k_wsplit0(const float* __restrict__ W0,
                          const float* __restrict__ skipW0) {
    int t = blockIdx.x * blockDim.x + threadIdx.x;
    if (t >= 320 * 256) return;              // K=640 -> 320 pair rows
    int p = t >> 8, d = t & 255;
    float f[2];
    #pragma unroll
    for (int e = 0; e < 2; e++) {
        int r = 2 * p + e;
        if (r < 512) { int h = r >> 7, c = r & 127; f[e] = W0[c * 1024 + h * 256 + d]; }
        else         { int c = r - 512;             f[e] = skipW0[c * 256 + d]; }
    }
    uint32_t hw, lw;
    split_pair(f[0], f[1], hw, lw);
    g_wbh[t] = hw; g_wbl[t] = lw;
}
__global__ void k_wsplit1(const float* __restrict__ W1) {
    int t = blockIdx.x * blockDim.x + threadIdx.x;
    if (t >= 512 * 256) return;              // K=1024 -> 512 pair rows
    int p = t >> 8, d = t & 255;
    float f[2];
    #pragma unroll
    for (int e = 0; e < 2; e++) {
        int r = 2 * p + e;
        int h = r >> 8, c = r & 255;
        f[e] = W1[c * 1024 + h * 256 + d];
    }
    uint32_t hw, lw;
    split_pair(f[0], f[1], hw, lw);
    g_wbh[t] = hw; g_wbl[t] = lw;
}

// ----------------------------------------------------- bf16-split MMA GEMM
__device__ __forceinline__ void mma_bf16(float* c, const uint32_t* a, const uint32_t* b) {
    asm volatile(
        "mma.sync.aligned.m16n8k16.row.col.f32.bf16.bf16.f32 "
        "{%0,%1,%2,%3}, {%4,%5,%6,%7}, {%8,%9}, {%0,%1,%2,%3};"
        : "+f"(c[0]), "+f"(c[1]), "+f"(c[2]), "+f"(c[3])
        : "r"(a[0]), "r"(a[1]), "r"(a[2]), "r"(a[3]), "r"(b[0]), "r"(b[1]));
}

// C = relu(A@B + b (+b2) (+g_h residual)).  A: g_y [M,K]. B: g_wbh/g_wbl.
// Tile 64(M) x 256(N) x 32(K). 256 threads, 8 warps (2m x 4n), warp 32x64.
// N == 256 fixed. grid = (1, ceil(M/64)) -> 313 blocks, single wave @ occ 2.
#define AW 20    // words per A row (16 data + 4 pad)
#define BW 264   // words per B pair-row (256 data + 8 pad); 264 % 32 == 8
__global__ void __launch_bounds__(256, 2) k_mma(const float* __restrict__ b,
                                                const float* __restrict__ b2,
                                                int add_sel,
                                                float* __restrict__ out_ext, int out_sel,
                                                int M, int K) {
    __shared__ uint32_t Ah[64 * AW], Al[64 * AW];
    __shared__ uint32_t Bh[16 * BW], Bl[16 * BW];
    const float* A = g_y;
    float* C = out_sel ? out_ext : g_h;

    int tid = threadIdx.x;
    int wid = tid >> 5, lane = tid & 31;
    int g   = lane >> 2;
    int tig = lane & 3;
    int warp_m = (wid >> 2) * 32;      // 0 or 32
    int warp_n = (wid & 3) * 64;       // 0,64,128,192
    int m0 = blockIdx.y * 64;

    float acc[2][8][4];
    #pragma unroll
    for (int i = 0; i < 2; i++)
        #pragma unroll
        for (int j = 0; j < 8; j++)
            #pragma unroll
            for (int q = 0; q < 4; q++) acc[i][j][q] = 0.f;

    // A loader: thread -> row tid/4 (0..63), k-segment (tid%4)*8
    int arow = tid >> 2;
    int akseg = (tid & 3) * 8;
    bool a_ok = (m0 + arow) < M;
    // B loader: pair-rows tid/32 and +8; col segments (tid%32)*4 and +128
    int bp = tid >> 5;
    int bn = (lane) * 4;

    for (int k0 = 0; k0 < K; k0 += 32) {
        // ---- A tile: 64x32 fp32 -> split bf16 hi/lo pair words ----
        {
            float f[8];
            if (a_ok) {
                const float4* Ap = (const float4*)(A + (size_t)(m0 + arow) * K + k0 + akseg);
                float4 v0 = Ap[0], v1 = Ap[1];
                f[0]=v0.x; f[1]=v0.y; f[2]=v0.z; f[3]=v0.w;
                f[4]=v1.x; f[5]=v1.y; f[6]=v1.z; f[7]=v1.w;
            } else {
                #pragma unroll
                for (int j = 0; j < 8; j++) f[j] = 0.f;
            }
            uint32_t hw[4], lw[4];
            #pragma unroll
            for (int j = 0; j < 4; j++) split_pair(f[2*j], f[2*j+1], hw[j], lw[j]);
            int base = arow * AW + (akseg >> 1);
            *(uint4*)&Ah[base] = make_uint4(hw[0], hw[1], hw[2], hw[3]);
            *(uint4*)&Al[base] = make_uint4(lw[0], lw[1], lw[2], lw[3]);
        }
        // ---- B tile: copy pre-split words, 16 pair-rows x 256 cols ----
        {
            int gp0 = (k0 >> 1);
            #pragma unroll
            for (int pp = 0; pp < 2; pp++) {
                int p = bp + 8 * pp;
                const uint4* srcH = (const uint4*)&g_wbh[(gp0 + p) * 256 + bn];
                const uint4* srcL = (const uint4*)&g_wbl[(gp0 + p) * 256 + bn];
                *(uint4*)&Bh[p * BW + bn]       = srcH[0];
                *(uint4*)&Bh[p * BW + bn + 128] = srcH[32];
                *(uint4*)&Bl[p * BW + bn]       = srcL[0];
                *(uint4*)&Bl[p * BW + bn + 128] = srcL[32];
            }
        }
        __syncthreads();

        #pragma unroll
        for (int kk2 = 0; kk2 < 2; kk2++) {       // two k16 steps
            int K0 = kk2 * 8;
            uint32_t ah[2][4], al[2][4];
            #pragma unroll
            for (int mt = 0; mt < 2; mt++) {
                int mr = warp_m + mt * 16 + g;
                ah[mt][0] = Ah[(mr)     * AW + K0 + tig];
                ah[mt][1] = Ah[(mr + 8) * AW + K0 + tig];
                ah[mt][2] = Ah[(mr)     * AW + K0 + 4 + tig];
                ah[mt][3] = Ah[(mr + 8) * AW + K0 + 4 + tig];
                al[mt][0] = Al[(mr)     * AW + K0 + tig];
                al[mt][1] = Al[(mr + 8) * AW + K0 + tig];
                al[mt][2] = Al[(mr)     * AW + K0 + 4 + tig];
                al[mt][3] = Al[(mr + 8) * AW + K0 + 4 + tig];
            }
            #pragma unroll
            for (int nt = 0; nt < 8; nt++) {
                int nc = warp_n + nt * 8 + g;
                uint32_t bh[2], bl[2];
                bh[0] = Bh[(K0 + tig)     * BW + nc];
                bh[1] = Bh[(K0 + 4 + tig) * BW + nc];
                bl[0] = Bl[(K0 + tig)     * BW + nc];
                bl[1] = Bl[(K0 + 4 + tig) * BW + nc];
                #pragma unroll
                for (int mt = 0; mt < 2; mt++) {
                    mma_bf16(acc[mt][nt], ah[mt], bl);
                    mma_bf16(acc[mt][nt], al[mt], bh);
                    mma_bf16(acc[mt][nt], ah[mt], bh);
                }
            }
        }
        __syncthreads();
    }

    // ---- fused epilogue: bias (+bias2) (+residual) + relu ----
    #pragma unroll
    for (int mt = 0; mt < 2; mt++) {
        int r = m0 + warp_m + mt * 16 + g;
        #pragma unroll
        for (int nt = 0; nt < 8; nt++) {
            int cc = warp_n + nt * 8 + tig * 2;
            float bb0 = b[cc], bb1 = b[cc + 1];
            if (b2) { bb0 += b2[cc]; bb1 += b2[cc + 1]; }
            if (r < M) {
                float v0 = acc[mt][nt][0] + bb0;
                float v1 = acc[mt][nt][1] + bb1;
                if (add_sel) {
                    v0 += g_h[(size_t)r * 256 + cc];
                    v1 += g_h[(size_t)r * 256 + cc + 1];
                }
                C[(size_t)r * 256 + cc]     = fmaxf(v0, 0.f);
                C[(size_t)r * 256 + cc + 1] = fmaxf(v1, 0.f);
            }
            if (r + 8 < M) {
                float v2 = acc[mt][nt][2] + bb0;
                float v3 = acc[mt][nt][3] + bb1;
                if (add_sel) {
                    v2 += g_h[(size_t)(r + 8) * 256 + cc];
                    v3 += g_h[(size_t)(r + 8) * 256 + cc + 1];
                }
                C[(size_t)(r + 8) * 256 + cc]     = fmaxf(v2, 0.f);
                C[(size_t)(r + 8) * 256 + cc + 1] = fmaxf(v3, 0.f);
            }
        }
    }
}

// -------------------------------------------------- edge_index passthrough
__global__ void k_copy_edges_f32(const int* __restrict__ ei,
                                 float* __restrict__ out, int n) {
    int t = blockIdx.x * blockDim.x + threadIdx.x;
    if (t < n) out[t] = (float)ei[t];
}

// ---------------------------------------------------------------- launcher
extern "C" void kernel_launch(void* const* d_in, const int* in_sizes, int n_in,
                              void* d_out, int out_size) {
    const float* x      = (const float*)d_in[0];
    const int*   ei     = (const int*)d_in[1];     // int32 (JAX x64 disabled)
    const float* W0     = (const float*)d_in[2];
    const float* u0     = (const float*)d_in[3];
    const float* c0     = (const float*)d_in[4];
    const float* b0     = (const float*)d_in[5];
    const float* skipW0 = (const float*)d_in[6];
    const float* skipb0 = (const float*)d_in[7];
    const float* W1     = (const float*)d_in[8];
    const float* u1     = (const float*)d_in[9];
    const float* c1     = (const float*)d_in[10];
    const float* b1     = (const float*)d_in[11];

    int N = in_sizes[0] / 128;
    int E = in_sizes[1] / 2;
    if (N > MAXN || E > MAXE) return;

    float* out = (float*)d_out;

    // CSR build
    k_init<<<(N + 255) / 256, 256>>>(N);
    k_hist<<<(E + 255) / 256, 256>>>(ei, E, N);
    k_scan<<<1, 1024>>>(N);
    k_fill<<<(E + N + 255) / 256, 256>>>(ei, E, N);

    // ---- conv0 ----
    k_wsplit0<<<(320 * 256 + 255) / 256, 256>>>(W0, skipW0);
    k_nodep<<<(N * 32 + 255) / 256, 256>>>(x, 0, u0, c0, 128, N);
    k_agg_in<128, 640><<<(N * 32 + 255) / 256, 256>>>(x, 0, N);
    {   // g_h = relu(z[:,0:640] @ Wstack0 + b0 + skipb0)
        dim3 grid(1, (N + 63) / 64);
        k_mma<<<grid, 256>>>(b0, skipb0, 0, (float*)nullptr, 0, N, 640);
    }

    // ---- conv1 ----
    k_wsplit1<<<(512 * 256 + 255) / 256, 256>>>(W1);
    k_nodep<<<(N * 32 + 255) / 256, 256>>>((const float*)nullptr, 1, u1, c1, 256, N);
    k_agg_in<256, 1024><<<(N * 32 + 255) / 256, 256>>>((const float*)nullptr, 1, N);
    {   // out = relu(z @ Wstack1 + b1 + g_h)
        dim3 grid(1, (N + 63) / 64);
        k_mma<<<grid, 256>>>(b1, (const float*)nullptr, 1, out, 1, N, 1024);
    }

    // edge_index passthrough
    long long hElems = (long long)N * 256;
    long long rem = (long long)out_size - hElems;
    if (rem >= 2LL * E) {
        k_copy_edges_f32<<<(2 * E + 255) / 256, 256>>>(ei, out + hElems, 2 * E);
    }
}

// round 8
// speedup vs baseline: 1.2079x; 1.2079x over previous
#include <cuda_runtime.h>
#include <cstdint>

// ---------------------------------------------------------------------------
// FeaStEncoderBlock, input-space aggregation + bf16-split tensor-core GEMM.
// Round 8: round-6 tiling (64x128, occ 3, 626 blocks — best packing) + the
// round-7 weight pre-split (g_wbh/g_wbl), with B smem fill via cp.async.
// ---------------------------------------------------------------------------

#define MAXN 20000
#define MAXE 320000

__device__ __align__(16) float    g_y[(size_t)MAXN * 1024];   // z buffer
__device__ __align__(16) float    g_h[(size_t)MAXN * 256];    // hidden h
__device__ __align__(16) uint32_t g_wbh[512 * 256];           // W hi bf16-pair words
__device__ __align__(16) uint32_t g_wbl[512 * 256];           // W lo bf16-pair words
__device__ __align__(16) float    g_ea[MAXN * 4];
__device__ __align__(16) float    g_eb[MAXN * 4];
__device__ int g_deg[MAXN];
__device__ int g_cur[MAXN];
__device__ int g_offs[MAXN + 1];
__device__ int g_srcs[MAXN + MAXE];

// ---------------------------------------------------------------- CSR build
__global__ void k_init(int n) {
    int i = blockIdx.x * blockDim.x + threadIdx.x;
    if (i < n) { g_deg[i] = 1; g_cur[i] = 0; }
}

__global__ void k_hist(const int* __restrict__ ei, int E, int n) {
    int t = blockIdx.x * blockDim.x + threadIdx.x;
    if (t < E) {
        int d = ei[E + t];
        if (d >= 0 && d < n) atomicAdd(&g_deg[d], 1);
    }
}

__global__ void k_scan(int n) {
    __shared__ int sh[1024];
    __shared__ int carry;
    if (threadIdx.x == 0) carry = 0;
    __syncthreads();
    int nchunks = (n + 1023) / 1024;
    for (int chunk = 0; chunk < nchunks; ++chunk) {
        int i = chunk * 1024 + threadIdx.x;
        int v = (i < n) ? g_deg[i] : 0;
        sh[threadIdx.x] = v;
        __syncthreads();
        #pragma unroll
        for (int off = 1; off < 1024; off <<= 1) {
            int t = (threadIdx.x >= off) ? sh[threadIdx.x - off] : 0;
            __syncthreads();
            sh[threadIdx.x] += t;
            __syncthreads();
        }
        int incl = sh[threadIdx.x] + carry;
        if (i < n) g_offs[i + 1] = incl;
        __syncthreads();
        if (threadIdx.x == 1023) carry = incl;
        __syncthreads();
    }
    if (threadIdx.x == 0) g_offs[0] = 0;
}

__global__ void k_fill(const int* __restrict__ ei, int E, int n) {
    int t = blockIdx.x * blockDim.x + threadIdx.x;
    if (t >= E + n) return;
    int s, d;
    if (t < E) { s = ei[t]; d = ei[E + t]; }
    else       { s = d = t - E; }
    if (s < 0 || s >= n || d < 0 || d >= n) return;
    int pos = g_offs[d] + atomicAdd(&g_cur[d], 1);
    g_srcs[pos] = s;
}

// -------------------------------------------- per-node attention projections
__global__ void k_nodep(const float* __restrict__ x_ext, int x_sel,
                        const float* __restrict__ u,
                        const float* __restrict__ c, int K, int n) {
    int warp = (blockIdx.x * blockDim.x + threadIdx.x) >> 5;
    int lane = threadIdx.x & 31;
    if (warp >= n) return;
    const float* x = x_sel ? g_h : x_ext;
    const float* xr = x + (size_t)warp * K;
    float a0 = 0.f, a1 = 0.f, a2 = 0.f, a3 = 0.f;
    for (int k = lane; k < K; k += 32) {
        float xv = xr[k];
        float4 uv = ((const float4*)u)[k];
        a0 += xv * uv.x; a1 += xv * uv.y; a2 += xv * uv.z; a3 += xv * uv.w;
    }
    #pragma unroll
    for (int off = 16; off; off >>= 1) {
        a0 += __shfl_down_sync(0xffffffffu, a0, off);
        a1 += __shfl_down_sync(0xffffffffu, a1, off);
        a2 += __shfl_down_sync(0xffffffffu, a2, off);
        a3 += __shfl_down_sync(0xffffffffu, a3, off);
    }
    if (lane == 0) {
        float4 ea, eb;
        ea.x = expf(a0 + c[0]); ea.y = expf(a1 + c[1]);
        ea.z = expf(a2 + c[2]); ea.w = expf(a3 + c[3]);
        eb.x = expf(-a0); eb.y = expf(-a1); eb.z = expf(-a2); eb.w = expf(-a3);
        ((float4*)g_ea)[warp] = ea;
        ((float4*)g_eb)[warp] = eb;
    }
}

// ------------------------------------------------ input-space aggregation
__device__ __forceinline__ float4 fma4(float4 a, float s, float4 v) {
    a.x += s * v.x; a.y += s * v.y; a.z += s * v.z; a.w += s * v.w; return a;
}

template<int IN, int ZC>
__global__ void k_agg_in(const float* __restrict__ x_ext, int x_sel, int n) {
    constexpr int V = IN / 128;
    int warp = (blockIdx.x * blockDim.x + threadIdx.x) >> 5;
    int lane = threadIdx.x & 31;
    if (warp >= n) return;
    const float* x = x_sel ? g_h : x_ext;
    int i  = warp;
    int s0 = g_offs[i], s1 = g_offs[i + 1];
    float4 ebi = ((const float4*)g_eb)[i];

    float4 acc[4][V];
    #pragma unroll
    for (int h = 0; h < 4; h++)
        #pragma unroll
        for (int v = 0; v < V; v++) acc[h][v] = make_float4(0.f, 0.f, 0.f, 0.f);

    for (int e = s0; e < s1; ++e) {
        int j = g_srcs[e];
        float4 a = ((const float4*)g_ea)[j];
        float q0 = a.x * ebi.x, q1 = a.y * ebi.y, q2 = a.z * ebi.z, q3 = a.w * ebi.w;
        float rz = 1.0f / (q0 + q1 + q2 + q3);
        q0 *= rz; q1 *= rz; q2 *= rz; q3 *= rz;
        const float4* xj = (const float4*)(x + (size_t)j * IN);
        #pragma unroll
        for (int v = 0; v < V; v++) {
            float4 xv = xj[lane + 32 * v];
            acc[0][v] = fma4(acc[0][v], q0, xv);
            acc[1][v] = fma4(acc[1][v], q1, xv);
            acc[2][v] = fma4(acc[2][v], q2, xv);
            acc[3][v] = fma4(acc[3][v], q3, xv);
        }
    }
    float inv = 1.0f / (float)(s1 - s0 > 0 ? s1 - s0 : 1);
    float4* z = (float4*)(g_y + (size_t)i * ZC);
    #pragma unroll
    for (int h = 0; h < 4; h++)
        #pragma unroll
        for (int v = 0; v < V; v++) {
            float4 r = acc[h][v];
            r.x *= inv; r.y *= inv; r.z *= inv; r.w *= inv;
            z[h * (IN / 4) + lane + 32 * v] = r;
        }
    if (ZC > 4 * IN) {
        const float4* xi = (const float4*)(x + (size_t)i * IN);
        #pragma unroll
        for (int v = 0; v < V; v++)
            z[IN + lane + 32 * v] = xi[lane + 32 * v];
    }
}

// -------------------------------------------------------- bf16 split utils
__device__ __forceinline__ uint32_t pack_bf16(float lo_elem, float hi_elem) {
    uint32_t r;
    asm("cvt.rn.bf16x2.f32 %0, %1, %2;" : "=r"(r) : "f"(hi_elem), "f"(lo_elem));
    return r;
}
// word packs (f0 -> lower 16 = k even, f1 -> upper 16 = k odd)
__device__ __forceinline__ void split_pair(float f0, float f1,
                                           uint32_t& hw, uint32_t& lw) {
    hw = pack_bf16(f0, f1);
    float h0 = __uint_as_float(hw << 16);
    float h1 = __uint_as_float(hw & 0xffff0000u);
    lw = pack_bf16(f0 - h0, f1 - h1);
}

// ------------------------------- stacked weight builders + bf16 pre-split
__global__ void k_wsplit0(const float* __restrict__ W0,
                          const float* __restrict__ skipW0) {
    int t = blockIdx.x * blockDim.x + threadIdx.x;
    if (t >= 320 * 256) return;              // K=640 -> 320 pair rows
    int p = t >> 8, d = t & 255;
    float f[2];
    #pragma unroll
    for (int e = 0; e < 2; e++) {
        int r = 2 * p + e;
        if (r < 512) { int h = r >> 7, c = r & 127; f[e] = W0[c * 1024 + h * 256 + d]; }
        else         { int c = r - 512;             f[e] = skipW0[c * 256 + d]; }
    }
    uint32_t hw, lw;
    split_pair(f[0], f[1], hw, lw);
    g_wbh[t] = hw; g_wbl[t] = lw;
}
__global__ void k_wsplit1(const float* __restrict__ W1) {
    int t = blockIdx.x * blockDim.x + threadIdx.x;
    if (t >= 512 * 256) return;              // K=1024 -> 512 pair rows
    int p = t >> 8, d = t & 255;
    float f[2];
    #pragma unroll
    for (int e = 0; e < 2; e++) {
        int r = 2 * p + e;
        int h = r >> 8, c = r & 255;
        f[e] = W1[c * 1024 + h * 256 + d];
    }
    uint32_t hw, lw;
    split_pair(f[0], f[1], hw, lw);
    g_wbh[t] = hw; g_wbl[t] = lw;
}

// ----------------------------------------------------- bf16-split MMA GEMM
__device__ __forceinline__ void mma_bf16(float* c, const uint32_t* a, const uint32_t* b) {
    asm volatile(
        "mma.sync.aligned.m16n8k16.row.col.f32.bf16.bf16.f32 "
        "{%0,%1,%2,%3}, {%4,%5,%6,%7}, {%8,%9}, {%0,%1,%2,%3};"
        : "+f"(c[0]), "+f"(c[1]), "+f"(c[2]), "+f"(c[3])
        : "r"(a[0]), "r"(a[1]), "r"(a[2]), "r"(a[3]), "r"(b[0]), "r"(b[1]));
}
__device__ __forceinline__ void cp_async16(uint32_t smem_addr, const void* gptr) {
    asm volatile("cp.async.cg.shared.global [%0], [%1], 16;"
                 :: "r"(smem_addr), "l"(gptr));
}

// C = relu(A@B + b (+b2) (+g_h residual)).  A: g_y [M,K]. B: g_wbh/g_wbl.
// Tile 64(M) x 128(N) x 32(K). 256 threads, 8 warps (2m x 4n), warp 32x32.
// grid = (2, ceil(M/64)) = 626 blocks, occ 3 (best packing: tail 1.18x).
#define AW 20    // words per A row (16 data + 4 pad)
#define BW 136   // words per B pair-row (128 data + 8 pad); 136 % 32 == 8
__global__ void __launch_bounds__(256, 3) k_mma(const float* __restrict__ b,
                                                const float* __restrict__ b2,
                                                int add_sel,
                                                float* __restrict__ out_ext, int out_sel,
                                                int M, int K) {
    __shared__ uint32_t Ah[64 * AW], Al[64 * AW];
    __shared__ uint32_t Bh[16 * BW], Bl[16 * BW];
    const float* A = g_y;
    float* C = out_sel ? out_ext : g_h;

    int tid = threadIdx.x;
    int wid = tid >> 5, lane = tid & 31;
    int g   = lane >> 2;
    int tig = lane & 3;
    int warp_m = (wid >> 2) * 32;
    int warp_n = (wid & 3) * 32;
    int m0 = blockIdx.y * 64;
    int n0 = blockIdx.x * 128;

    float acc[2][4][4];
    #pragma unroll
    for (int i = 0; i < 2; i++)
        #pragma unroll
        for (int j = 0; j < 4; j++)
            #pragma unroll
            for (int q = 0; q < 4; q++) acc[i][j][q] = 0.f;

    // A loader: thread -> row tid/4 (0..63), k-segment (tid%4)*8
    int arow = tid >> 2;
    int akseg = (tid & 3) * 8;
    bool a_ok = (m0 + arow) < M;
    // B loader: pair-rows tid/32 and +8; cols (tid%32)*4 (4 words = 16B)
    int bp = tid >> 5;
    int bn = (lane) * 4;
    uint32_t bh0_s = (uint32_t)__cvta_generic_to_shared(&Bh[bp * BW + bn]);
    uint32_t bh1_s = (uint32_t)__cvta_generic_to_shared(&Bh[(bp + 8) * BW + bn]);
    uint32_t bl0_s = (uint32_t)__cvta_generic_to_shared(&Bl[bp * BW + bn]);
    uint32_t bl1_s = (uint32_t)__cvta_generic_to_shared(&Bl[(bp + 8) * BW + bn]);

    for (int k0 = 0; k0 < K; k0 += 32) {
        // ---- B tile: async copy of pre-split words (overlaps A work) ----
        {
            int gp0 = (k0 >> 1);
            const uint32_t* srcH0 = &g_wbh[(gp0 + bp) * 256 + n0 + bn];
            const uint32_t* srcH1 = &g_wbh[(gp0 + bp + 8) * 256 + n0 + bn];
            const uint32_t* srcL0 = &g_wbl[(gp0 + bp) * 256 + n0 + bn];
            const uint32_t* srcL1 = &g_wbl[(gp0 + bp + 8) * 256 + n0 + bn];
            cp_async16(bh0_s, srcH0);
            cp_async16(bh1_s, srcH1);
            cp_async16(bl0_s, srcL0);
            cp_async16(bl1_s, srcL1);
            asm volatile("cp.async.commit_group;");
        }
        // ---- A tile: 64x32 fp32 -> split bf16 hi/lo pair words ----
        {
            float f[8];
            if (a_ok) {
                const float4* Ap = (const float4*)(A + (size_t)(m0 + arow) * K + k0 + akseg);
                float4 v0 = Ap[0], v1 = Ap[1];
                f[0]=v0.x; f[1]=v0.y; f[2]=v0.z; f[3]=v0.w;
                f[4]=v1.x; f[5]=v1.y; f[6]=v1.z; f[7]=v1.w;
            } else {
                #pragma unroll
                for (int j = 0; j < 8; j++) f[j] = 0.f;
            }
            uint32_t hw[4], lw[4];
            #pragma unroll
            for (int j = 0; j < 4; j++) split_pair(f[2*j], f[2*j+1], hw[j], lw[j]);
            int base = arow * AW + (akseg >> 1);
            *(uint4*)&Ah[base] = make_uint4(hw[0], hw[1], hw[2], hw[3]);
            *(uint4*)&Al[base] = make_uint4(lw[0], lw[1], lw[2], lw[3]);
        }
        asm volatile("cp.async.wait_group 0;");
        __syncthreads();

        #pragma unroll
        for (int kk2 = 0; kk2 < 2; kk2++) {       // two k16 steps
            int K0 = kk2 * 8;
            uint32_t ah[2][4], al[2][4];
            #pragma unroll
            for (int mt = 0; mt < 2; mt++) {
                int mr = warp_m + mt * 16 + g;
                ah[mt][0] = Ah[(mr)     * AW + K0 + tig];
                ah[mt][1] = Ah[(mr + 8) * AW + K0 + tig];
                ah[mt][2] = Ah[(mr)     * AW + K0 + 4 + tig];
                ah[mt][3] = Ah[(mr + 8) * AW + K0 + 4 + tig];
                al[mt][0] = Al[(mr)     * AW + K0 + tig];
                al[mt][1] = Al[(mr + 8) * AW + K0 + tig];
                al[mt][2] = Al[(mr)     * AW + K0 + 4 + tig];
                al[mt][3] = Al[(mr + 8) * AW + K0 + 4 + tig];
            }
            #pragma unroll
            for (int nt = 0; nt < 4; nt++) {
                int nc = warp_n + nt * 8 + g;
                uint32_t bh[2], bl[2];
                bh[0] = Bh[(K0 + tig)     * BW + nc];
                bh[1] = Bh[(K0 + 4 + tig) * BW + nc];
                bl[0] = Bl[(K0 + tig)     * BW + nc];
                bl[1] = Bl[(K0 + 4 + tig) * BW + nc];
                #pragma unroll
                for (int mt = 0; mt < 2; mt++) {
                    mma_bf16(acc[mt][nt], ah[mt], bl);
                    mma_bf16(acc[mt][nt], al[mt], bh);
                    mma_bf16(acc[mt][nt], ah[mt], bh);
                }
            }
        }
        __syncthreads();
    }

    // ---- fused epilogue: bias (+bias2) (+residual) + relu ----
    #pragma unroll
    for (int mt = 0; mt < 2; mt++) {
        int r = m0 + warp_m + mt * 16 + g;
        #pragma unroll
        for (int nt = 0; nt < 4; nt++) {
            int cc = n0 + warp_n + nt * 8 + tig * 2;
            float bb0 = b[cc], bb1 = b[cc + 1];
            if (b2) { bb0 += b2[cc]; bb1 += b2[cc + 1]; }
            if (r < M) {
                float v0 = acc[mt][nt][0] + bb0;
                float v1 = acc[mt][nt][1] + bb1;
                if (add_sel) {
                    v0 += g_h[(size_t)r * 256 + cc];
                    v1 += g_h[(size_t)r * 256 + cc + 1];
                }
                C[(size_t)r * 256 + cc]     = fmaxf(v0, 0.f);
                C[(size_t)r * 256 + cc + 1] = fmaxf(v1, 0.f);
            }
            if (r + 8 < M) {
                float v2 = acc[mt][nt][2] + bb0;
                float v3 = acc[mt][nt][3] + bb1;
                if (add_sel) {
                    v2 += g_h[(size_t)(r + 8) * 256 + cc];
                    v3 += g_h[(size_t)(r + 8) * 256 + cc + 1];
                }
                C[(size_t)(r + 8) * 256 + cc]     = fmaxf(v2, 0.f);
                C[(size_t)(r + 8) * 256 + cc + 1] = fmaxf(v3, 0.f);
            }
        }
    }
}

// -------------------------------------------------- edge_index passthrough
__global__ void k_copy_edges_f32(const int* __restrict__ ei,
                                 float* __restrict__ out, int n) {
    int t = blockIdx.x * blockDim.x + threadIdx.x;
    if (t < n) out[t] = (float)ei[t];
}

// ---------------------------------------------------------------- launcher
extern "C" void kernel_launch(void* const* d_in, const int* in_sizes, int n_in,
                              void* d_out, int out_size) {
    const float* x      = (const float*)d_in[0];
    const int*   ei     = (const int*)d_in[1];     // int32 (JAX x64 disabled)
    const float* W0     = (const float*)d_in[2];
    const float* u0     = (const float*)d_in[3];
    const float* c0     = (const float*)d_in[4];
    const float* b0     = (const float*)d_in[5];
    const float* skipW0 = (const float*)d_in[6];
    const float* skipb0 = (const float*)d_in[7];
    const float* W1     = (const float*)d_in[8];
    const float* u1     = (const float*)d_in[9];
    const float* c1     = (const float*)d_in[10];
    const float* b1     = (const float*)d_in[11];

    int N = in_sizes[0] / 128;
    int E = in_sizes[1] / 2;
    if (N > MAXN || E > MAXE) return;

    float* out = (float*)d_out;

    // CSR build
    k_init<<<(N + 255) / 256, 256>>>(N);
    k_hist<<<(E + 255) / 256, 256>>>(ei, E, N);
    k_scan<<<1, 1024>>>(N);
    k_fill<<<(E + N + 255) / 256, 256>>>(ei, E, N);

    // ---- conv0 ----
    k_wsplit0<<<(320 * 256 + 255) / 256, 256>>>(W0, skipW0);
    k_nodep<<<(N * 32 + 255) / 256, 256>>>(x, 0, u0, c0, 128, N);
    k_agg_in<128, 640><<<(N * 32 + 255) / 256, 256>>>(x, 0, N);
    {   // g_h = relu(z[:,0:640] @ Wstack0 + b0 + skipb0)
        dim3 grid(2, (N + 63) / 64);
        k_mma<<<grid, 256>>>(b0, skipb0, 0, (float*)nullptr, 0, N, 640);
    }

    // ---- conv1 ----
    k_wsplit1<<<(512 * 256 + 255) / 256, 256>>>(W1);
    k_nodep<<<(N * 32 + 255) / 256, 256>>>((const float*)nullptr, 1, u1, c1, 256, N);
    k_agg_in<256, 1024><<<(N * 32 + 255) / 256, 256>>>((const float*)nullptr, 1, N);
    {   // out = relu(z @ Wstack1 + b1 + g_h)
        dim3 grid(2, (N + 63) / 64);
        k_mma<<<grid, 256>>>(b1, (const float*)nullptr, 1, out, 1, N, 1024);
    }

    // edge_index passthrough
    long long hElems = (long long)N * 256;
    long long rem = (long long)out_size - hElems;
    if (rem >= 2LL * E) {
        k_copy_edges_f32<<<(2 * E + 255) / 256, 256>>>(ei, out + hElems, 2 * E);
    }
}

// round 10
// speedup vs baseline: 1.2872x; 1.0656x over previous
#include <cuda_runtime.h>
#include <cstdint>

// ---------------------------------------------------------------------------
// FeaStEncoderBlock, input-space aggregation + bf16-split tensor-core GEMM.
// Round 10 (tcgen05 unavailable: harness emits compute_103 PTX):
//   - z written PRE-SPLIT as bf16 hi/lo pair-words (g_yh/g_yl) by k_agg_in;
//     GEMM A-path is now a pure cp.async copy (no mainloop conversion).
//   - warp-shuffle scan (was ~400 barriers, now ~80).
//   - edge-index/ea prefetch in the aggregation loop.
// GEMM: proven round-8 structure (64x128 tile, BK=32, occ 3, 626 blocks).
// ---------------------------------------------------------------------------

#define MAXN 20000
#define MAXE 320000

__device__ __align__(16) uint32_t g_yh[(size_t)MAXN * 512];   // z hi pair-words
__device__ __align__(16) uint32_t g_yl[(size_t)MAXN * 512];   // z lo pair-words
__device__ __align__(16) float    g_h[(size_t)MAXN * 256];    // hidden h
__device__ __align__(16) uint32_t g_wbh[512 * 256];           // W hi bf16-pair words
__device__ __align__(16) uint32_t g_wbl[512 * 256];           // W lo bf16-pair words
__device__ __align__(16) float    g_ea[MAXN * 4];
__device__ __align__(16) float    g_eb[MAXN * 4];
__device__ int g_deg[MAXN];
__device__ int g_cur[MAXN];
__device__ int g_offs[MAXN + 1];
__device__ int g_srcs[MAXN + MAXE];

// ---------------------------------------------------------------- CSR build
__global__ void k_init(int n) {
    int i = blockIdx.x * blockDim.x + threadIdx.x;
    if (i < n) { g_deg[i] = 1; g_cur[i] = 0; }
}

__global__ void k_hist(const int* __restrict__ ei, int E, int n) {
    int t = blockIdx.x * blockDim.x + threadIdx.x;
    if (t < E) {
        int d = ei[E + t];
        if (d >= 0 && d < n) atomicAdd(&g_deg[d], 1);
    }
}

// single-block exclusive scan, warp-shuffle based
__global__ void k_scan(int n) {
    __shared__ int wsum[32];
    __shared__ int carry;
    int tid = threadIdx.x, lane = tid & 31, w = tid >> 5;
    if (tid == 0) carry = 0;
    __syncthreads();
    int nchunks = (n + 1023) >> 10;
    for (int ch = 0; ch < nchunks; ++ch) {
        int i = ch * 1024 + tid;
        int v = (i < n) ? g_deg[i] : 0;
        int s = v;
        #pragma unroll
        for (int o = 1; o < 32; o <<= 1) {
            int t = __shfl_up_sync(0xffffffffu, s, o);
            if (lane >= o) s += t;
        }
        if (lane == 31) wsum[w] = s;
        __syncthreads();
        if (w == 0) {
            int ws = wsum[lane];
            #pragma unroll
            for (int o = 1; o < 32; o <<= 1) {
                int t = __shfl_up_sync(0xffffffffu, ws, o);
                if (lane >= o) ws += t;
            }
            wsum[lane] = ws;
        }
        __syncthreads();
        int incl = s + (w ? wsum[w - 1] : 0) + carry;
        if (i < n) g_offs[i + 1] = incl;
        __syncthreads();
        if (tid == 1023) carry = incl;
        __syncthreads();
    }
    if (threadIdx.x == 0) g_offs[0] = 0;
}

__global__ void k_fill(const int* __restrict__ ei, int E, int n) {
    int t = blockIdx.x * blockDim.x + threadIdx.x;
    if (t >= E + n) return;
    int s, d;
    if (t < E) { s = ei[t]; d = ei[E + t]; }
    else       { s = d = t - E; }
    if (s < 0 || s >= n || d < 0 || d >= n) return;
    int pos = g_offs[d] + atomicAdd(&g_cur[d], 1);
    g_srcs[pos] = s;
}

// -------------------------------------------- per-node attention projections
__global__ void k_nodep(const float* __restrict__ x_ext, int x_sel,
                        const float* __restrict__ u,
                        const float* __restrict__ c, int K, int n) {
    int warp = (blockIdx.x * blockDim.x + threadIdx.x) >> 5;
    int lane = threadIdx.x & 31;
    if (warp >= n) return;
    const float* x = x_sel ? g_h : x_ext;
    const float* xr = x + (size_t)warp * K;
    float a0 = 0.f, a1 = 0.f, a2 = 0.f, a3 = 0.f;
    for (int k = lane; k < K; k += 32) {
        float xv = xr[k];
        float4 uv = ((const float4*)u)[k];
        a0 += xv * uv.x; a1 += xv * uv.y; a2 += xv * uv.z; a3 += xv * uv.w;
    }
    #pragma unroll
    for (int off = 16; off; off >>= 1) {
        a0 += __shfl_down_sync(0xffffffffu, a0, off);
        a1 += __shfl_down_sync(0xffffffffu, a1, off);
        a2 += __shfl_down_sync(0xffffffffu, a2, off);
        a3 += __shfl_down_sync(0xffffffffu, a3, off);
    }
    if (lane == 0) {
        float4 ea, eb;
        ea.x = expf(a0 + c[0]); ea.y = expf(a1 + c[1]);
        ea.z = expf(a2 + c[2]); ea.w = expf(a3 + c[3]);
        eb.x = expf(-a0); eb.y = expf(-a1); eb.z = expf(-a2); eb.w = expf(-a3);
        ((float4*)g_ea)[warp] = ea;
        ((float4*)g_eb)[warp] = eb;
    }
}

// -------------------------------------------------------- bf16 split utils
__device__ __forceinline__ uint32_t pack_bf16(float lo_elem, float hi_elem) {
    uint32_t r;
    asm("cvt.rn.bf16x2.f32 %0, %1, %2;" : "=r"(r) : "f"(hi_elem), "f"(lo_elem));
    return r;
}
// word packs (f0 -> lower 16 = k even, f1 -> upper 16 = k odd)
__device__ __forceinline__ void split_pair(float f0, float f1,
                                           uint32_t& hw, uint32_t& lw) {
    hw = pack_bf16(f0, f1);
    float h0 = __uint_as_float(hw << 16);
    float h1 = __uint_as_float(hw & 0xffff0000u);
    lw = pack_bf16(f0 - h0, f1 - h1);
}

// ------------------------------------------------ input-space aggregation
// One warp per node. Writes z PRE-SPLIT to g_yh/g_yl (bf16 pair-words,
// row stride 512 words). Skip-concat tail (conv0) also split.
__device__ __forceinline__ float4 fma4(float4 a, float s, float4 v) {
    a.x += s * v.x; a.y += s * v.y; a.z += s * v.z; a.w += s * v.w; return a;
}
__device__ __forceinline__ void store_split4(uint32_t* dh, uint32_t* dl, float4 r) {
    uint32_t h0, l0, h1, l1;
    split_pair(r.x, r.y, h0, l0);
    split_pair(r.z, r.w, h1, l1);
    *(uint2*)dh = make_uint2(h0, h1);
    *(uint2*)dl = make_uint2(l0, l1);
}

template<int IN, int ZC>
__global__ void k_agg_in(const float* __restrict__ x_ext, int x_sel, int n) {
    constexpr int V = IN / 128;
    int warp = (blockIdx.x * blockDim.x + threadIdx.x) >> 5;
    int lane = threadIdx.x & 31;
    if (warp >= n) return;
    const float* x = x_sel ? g_h : x_ext;
    int i  = warp;
    int s0 = g_offs[i], s1 = g_offs[i + 1];
    float4 ebi = ((const float4*)g_eb)[i];

    float4 acc[4][V];
    #pragma unroll
    for (int h = 0; h < 4; h++)
        #pragma unroll
        for (int v = 0; v < V; v++) acc[h][v] = make_float4(0.f, 0.f, 0.f, 0.f);

    // software-pipelined edge loop: prefetch next index + ea
    int j = (s0 < s1) ? g_srcs[s0] : 0;
    float4 a = ((const float4*)g_ea)[j];
    for (int e = s0; e < s1; ++e) {
        int jn = 0; float4 an = a;
        if (e + 1 < s1) {
            jn = g_srcs[e + 1];
            an = ((const float4*)g_ea)[jn];
        }
        float q0 = a.x * ebi.x, q1 = a.y * ebi.y, q2 = a.z * ebi.z, q3 = a.w * ebi.w;
        float rz = 1.0f / (q0 + q1 + q2 + q3);
        q0 *= rz; q1 *= rz; q2 *= rz; q3 *= rz;
        const float4* xj = (const float4*)(x + (size_t)j * IN);
        #pragma unroll
        for (int v = 0; v < V; v++) {
            float4 xv = xj[lane + 32 * v];
            acc[0][v] = fma4(acc[0][v], q0, xv);
            acc[1][v] = fma4(acc[1][v], q1, xv);
            acc[2][v] = fma4(acc[2][v], q2, xv);
            acc[3][v] = fma4(acc[3][v], q3, xv);
        }
        j = jn; a = an;
    }
    float inv = 1.0f / (float)(s1 - s0 > 0 ? s1 - s0 : 1);
    uint32_t* zh = g_yh + (size_t)i * 512;
    uint32_t* zl = g_yl + (size_t)i * 512;
    #pragma unroll
    for (int h = 0; h < 4; h++)
        #pragma unroll
        for (int v = 0; v < V; v++) {
            float4 r = acc[h][v];
            r.x *= inv; r.y *= inv; r.z *= inv; r.w *= inv;
            int wi = (h * IN) / 2 + 2 * (lane + 32 * v);
            store_split4(zh + wi, zl + wi, r);
        }
    if (ZC > 4 * IN) {
        const float4* xi = (const float4*)(x + (size_t)i * IN);
        #pragma unroll
        for (int v = 0; v < V; v++) {
            float4 r = xi[lane + 32 * v];
            int wi = 2 * IN + 2 * (lane + 32 * v);
            store_split4(zh + wi, zl + wi, r);
        }
    }
}

// ------------------------------- stacked weight builders + bf16 pre-split
__global__ void k_wsplit0(const float* __restrict__ W0,
                          const float* __restrict__ skipW0) {
    int t = blockIdx.x * blockDim.x + threadIdx.x;
    if (t >= 320 * 256) return;              // K=640 -> 320 pair rows
    int p = t >> 8, d = t & 255;
    float f[2];
    #pragma unroll
    for (int e = 0; e < 2; e++) {
        int r = 2 * p + e;
        if (r < 512) { int h = r >> 7, c = r & 127; f[e] = W0[c * 1024 + h * 256 + d]; }
        else         { int c = r - 512;             f[e] = skipW0[c * 256 + d]; }
    }
    uint32_t hw, lw;
    split_pair(f[0], f[1], hw, lw);
    g_wbh[t] = hw; g_wbl[t] = lw;
}
__global__ void k_wsplit1(const float* __restrict__ W1) {
    int t = blockIdx.x * blockDim.x + threadIdx.x;
    if (t >= 512 * 256) return;              // K=1024 -> 512 pair rows
    int p = t >> 8, d = t & 255;
    float f[2];
    #pragma unroll
    for (int e = 0; e < 2; e++) {
        int r = 2 * p + e;
        int h = r >> 8, c = r & 255;
        f[e] = W1[c * 1024 + h * 256 + d];
    }
    uint32_t hw, lw;
    split_pair(f[0], f[1], hw, lw);
    g_wbh[t] = hw; g_wbl[t] = lw;
}

// ----------------------------------------------------- bf16-split MMA GEMM
__device__ __forceinline__ void mma_bf16(float* c, const uint32_t* a, const uint32_t* b) {
    asm volatile(
        "mma.sync.aligned.m16n8k16.row.col.f32.bf16.bf16.f32 "
        "{%0,%1,%2,%3}, {%4,%5,%6,%7}, {%8,%9}, {%0,%1,%2,%3};"
        : "+f"(c[0]), "+f"(c[1]), "+f"(c[2]), "+f"(c[3])
        : "r"(a[0]), "r"(a[1]), "r"(a[2]), "r"(a[3]), "r"(b[0]), "r"(b[1]));
}
__device__ __forceinline__ void cp_async16(uint32_t smem_addr, const void* gptr) {
    asm volatile("cp.async.cg.shared.global [%0], [%1], 16;"
                 :: "r"(smem_addr), "l"(gptr));
}

// C = relu(A@B + b (+b2) (+g_h residual)).  A: g_yh/g_yl. B: g_wbh/g_wbl.
// Tile 64(M) x 128(N) x 32(K). 256 threads, 8 warps (2m x 4n), warp 32x32.
// grid = (2, ceil(M/64)) = 626 blocks, occ 3. Entire smem fill is cp.async.
#define AW 20    // words per A row (16 data + 4 pad)
#define BW 136   // words per B pair-row (128 data + 8 pad); 136 % 32 == 8
__global__ void __launch_bounds__(256, 3) k_mma(const float* __restrict__ b,
                                                const float* __restrict__ b2,
                                                int add_sel,
                                                float* __restrict__ out_ext, int out_sel,
                                                int M, int K) {
    __shared__ uint32_t Ah[64 * AW], Al[64 * AW];
    __shared__ uint32_t Bh[16 * BW], Bl[16 * BW];
    float* C = out_sel ? out_ext : g_h;

    int tid = threadIdx.x;
    int wid = tid >> 5, lane = tid & 31;
    int g   = lane >> 2;
    int tig = lane & 3;
    int warp_m = (wid >> 2) * 32;
    int warp_n = (wid & 3) * 32;
    int m0 = blockIdx.y * 64;
    int n0 = blockIdx.x * 128;

    float acc[2][4][4];
    #pragma unroll
    for (int i = 0; i < 2; i++)
        #pragma unroll
        for (int j = 0; j < 4; j++)
            #pragma unroll
            for (int q = 0; q < 4; q++) acc[i][j][q] = 0.f;

    // A loader: thread -> row tid/4 (0..63), 4 pair-words at (tid%4)*4
    int arow = tid >> 2;
    int aseg = (tid & 3) * 4;
    bool a_ok = (m0 + arow) < M;
    uint32_t ah_s = (uint32_t)__cvta_generic_to_shared(&Ah[arow * AW + aseg]);
    uint32_t al_s = (uint32_t)__cvta_generic_to_shared(&Al[arow * AW + aseg]);
    // B loader: pair-rows tid/32 and +8; cols (tid%32)*4 (4 words = 16B)
    int bp = tid >> 5;
    int bn = lane * 4;
    uint32_t bh0_s = (uint32_t)__cvta_generic_to_shared(&Bh[bp * BW + bn]);
    uint32_t bh1_s = (uint32_t)__cvta_generic_to_shared(&Bh[(bp + 8) * BW + bn]);
    uint32_t bl0_s = (uint32_t)__cvta_generic_to_shared(&Bl[bp * BW + bn]);
    uint32_t bl1_s = (uint32_t)__cvta_generic_to_shared(&Bl[(bp + 8) * BW + bn]);

    for (int k0 = 0; k0 < K; k0 += 32) {
        // ---- B tile: async copy of pre-split weight words ----
        {
            int gp0 = (k0 >> 1);
            cp_async16(bh0_s, &g_wbh[(gp0 + bp) * 256 + n0 + bn]);
            cp_async16(bh1_s, &g_wbh[(gp0 + bp + 8) * 256 + n0 + bn]);
            cp_async16(bl0_s, &g_wbl[(gp0 + bp) * 256 + n0 + bn]);
            cp_async16(bl1_s, &g_wbl[(gp0 + bp + 8) * 256 + n0 + bn]);
        }
        // ---- A tile: async copy of pre-split z words ----
        if (a_ok) {
            size_t gw = (size_t)(m0 + arow) * 512 + (k0 >> 1) + aseg;
            cp_async16(ah_s, &g_yh[gw]);
            cp_async16(al_s, &g_yl[gw]);
        } else {
            *(uint4*)&Ah[arow * AW + aseg] = make_uint4(0, 0, 0, 0);
            *(uint4*)&Al[arow * AW + aseg] = make_uint4(0, 0, 0, 0);
        }
        asm volatile("cp.async.commit_group;");
        asm volatile("cp.async.wait_group 0;");
        __syncthreads();

        #pragma unroll
        for (int kk2 = 0; kk2 < 2; kk2++) {       // two k16 steps
            int K0 = kk2 * 8;
            uint32_t ah[2][4], al[2][4];
            #pragma unroll
            for (int mt = 0; mt < 2; mt++) {
                int mr = warp_m + mt * 16 + g;
                ah[mt][0] = Ah[(mr)     * AW + K0 + tig];
                ah[mt][1] = Ah[(mr + 8) * AW + K0 + tig];
                ah[mt][2] = Ah[(mr)     * AW + K0 + 4 + tig];
                ah[mt][3] = Ah[(mr + 8) * AW + K0 + 4 + tig];
                al[mt][0] = Al[(mr)     * AW + K0 + tig];
                al[mt][1] = Al[(mr + 8) * AW + K0 + tig];
                al[mt][2] = Al[(mr)     * AW + K0 + 4 + tig];
                al[mt][3] = Al[(mr + 8) * AW + K0 + 4 + tig];
            }
            #pragma unroll
            for (int nt = 0; nt < 4; nt++) {
                int nc = warp_n + nt * 8 + g;
                uint32_t bh[2], bl[2];
                bh[0] = Bh[(K0 + tig)     * BW + nc];
                bh[1] = Bh[(K0 + 4 + tig) * BW + nc];
                bl[0] = Bl[(K0 + tig)     * BW + nc];
                bl[1] = Bl[(K0 + 4 + tig) * BW + nc];
                #pragma unroll
                for (int mt = 0; mt < 2; mt++) {
                    mma_bf16(acc[mt][nt], ah[mt], bl);
                    mma_bf16(acc[mt][nt], al[mt], bh);
                    mma_bf16(acc[mt][nt], ah[mt], bh);
                }
            }
        }
        __syncthreads();
    }

    // ---- fused epilogue: bias (+bias2) (+residual) + relu ----
    #pragma unroll
    for (int mt = 0; mt < 2; mt++) {
        int r = m0 + warp_m + mt * 16 + g;
        #pragma unroll
        for (int nt = 0; nt < 4; nt++) {
            int cc = n0 + warp_n + nt * 8 + tig * 2;
            float bb0 = b[cc], bb1 = b[cc + 1];
            if (b2) { bb0 += b2[cc]; bb1 += b2[cc + 1]; }
            if (r < M) {
                float v0 = acc[mt][nt][0] + bb0;
                float v1 = acc[mt][nt][1] + bb1;
                if (add_sel) {
                    v0 += g_h[(size_t)r * 256 + cc];
                    v1 += g_h[(size_t)r * 256 + cc + 1];
                }
                C[(size_t)r * 256 + cc]     = fmaxf(v0, 0.f);
                C[(size_t)r * 256 + cc + 1] = fmaxf(v1, 0.f);
            }
            if (r + 8 < M) {
                float v2 = acc[mt][nt][2] + bb0;
                float v3 = acc[mt][nt][3] + bb1;
                if (add_sel) {
                    v2 += g_h[(size_t)(r + 8) * 256 + cc];
                    v3 += g_h[(size_t)(r + 8) * 256 + cc + 1];
                }
                C[(size_t)(r + 8) * 256 + cc]     = fmaxf(v2, 0.f);
                C[(size_t)(r + 8) * 256 + cc + 1] = fmaxf(v3, 0.f);
            }
        }
    }
}

// -------------------------------------------------- edge_index passthrough
__global__ void k_copy_edges_f32(const int* __restrict__ ei,
                                 float* __restrict__ out, int n) {
    int t = blockIdx.x * blockDim.x + threadIdx.x;
    if (t < n) out[t] = (float)ei[t];
}

// ---------------------------------------------------------------- launcher
extern "C" void kernel_launch(void* const* d_in, const int* in_sizes, int n_in,
                              void* d_out, int out_size) {
    const float* x      = (const float*)d_in[0];
    const int*   ei     = (const int*)d_in[1];     // int32 (JAX x64 disabled)
    const float* W0     = (const float*)d_in[2];
    const float* u0     = (const float*)d_in[3];
    const float* c0     = (const float*)d_in[4];
    const float* b0     = (const float*)d_in[5];
    const float* skipW0 = (const float*)d_in[6];
    const float* skipb0 = (const float*)d_in[7];
    const float* W1     = (const float*)d_in[8];
    const float* u1     = (const float*)d_in[9];
    const float* c1     = (const float*)d_in[10];
    const float* b1     = (const float*)d_in[11];

    int N = in_sizes[0] / 128;
    int E = in_sizes[1] / 2;
    if (N > MAXN || E > MAXE) return;

    float* out = (float*)d_out;

    // CSR build
    k_init<<<(N + 255) / 256, 256>>>(N);
    k_hist<<<(E + 255) / 256, 256>>>(ei, E, N);
    k_scan<<<1, 1024>>>(N);
    k_fill<<<(E + N + 255) / 256, 256>>>(ei, E, N);

    // ---- conv0 ----
    k_wsplit0<<<(320 * 256 + 255) / 256, 256>>>(W0, skipW0);
    k_nodep<<<(N * 32 + 255) / 256, 256>>>(x, 0, u0, c0, 128, N);
    k_agg_in<128, 640><<<(N * 32 + 255) / 256, 256>>>(x, 0, N);
    {   // g_h = relu(z[:,0:640] @ Wstack0 + b0 + skipb0)
        dim3 grid(2, (N + 63) / 64);
        k_mma<<<grid, 256>>>(b0, skipb0, 0, (float*)nullptr, 0, N, 640);
    }

    // ---- conv1 ----
    k_wsplit1<<<(512 * 256 + 255) / 256, 256>>>(W1);
    k_nodep<<<(N * 32 + 255) / 256, 256>>>((const float*)nullptr, 1, u1, c1, 256, N);
    k_agg_in<256, 1024><<<(N * 32 + 255) / 256, 256>>>((const float*)nullptr, 1, N);
    {   // out = relu(z @ Wstack1 + b1 + g_h)
        dim3 grid(2, (N + 63) / 64);
        k_mma<<<grid, 256>>>(b1, (const float*)nullptr, 1, out, 1, N, 1024);
    }

    // edge_index passthrough
    long long hElems = (long long)N * 256;
    long long rem = (long long)out_size - hElems;
    if (rem >= 2LL * E) {
        k_copy_edges_f32<<<(2 * E + 255) / 256, 256>>>(ei, out + hElems, 2 * E);
    }
}

// round 11
// speedup vs baseline: 1.3127x; 1.0198x over previous
#include <cuda_runtime.h>
#include <cstdint>

// ---------------------------------------------------------------------------
// FeaStEncoderBlock, input-space aggregation + bf16-split tensor-core GEMM.
// Round 11: GEMM gets 2-stage cp.async double-buffering (dynamic smem,
// 55.3KB/block, occ 3). Everything else identical to round 10 (345.7us).
// ---------------------------------------------------------------------------

#define MAXN 20000
#define MAXE 320000

__device__ __align__(16) uint32_t g_yh[(size_t)MAXN * 512];   // z hi pair-words
__device__ __align__(16) uint32_t g_yl[(size_t)MAXN * 512];   // z lo pair-words
__device__ __align__(16) float    g_h[(size_t)MAXN * 256];    // hidden h
__device__ __align__(16) uint32_t g_wbh[512 * 256];           // W hi bf16-pair words
__device__ __align__(16) uint32_t g_wbl[512 * 256];           // W lo bf16-pair words
__device__ __align__(16) float    g_ea[MAXN * 4];
__device__ __align__(16) float    g_eb[MAXN * 4];
__device__ int g_deg[MAXN];
__device__ int g_cur[MAXN];
__device__ int g_offs[MAXN + 1];
__device__ int g_srcs[MAXN + MAXE];

// ---------------------------------------------------------------- CSR build
__global__ void k_init(int n) {
    int i = blockIdx.x * blockDim.x + threadIdx.x;
    if (i < n) { g_deg[i] = 1; g_cur[i] = 0; }
}

__global__ void k_hist(const int* __restrict__ ei, int E, int n) {
    int t = blockIdx.x * blockDim.x + threadIdx.x;
    if (t < E) {
        int d = ei[E + t];
        if (d >= 0 && d < n) atomicAdd(&g_deg[d], 1);
    }
}

// single-block exclusive scan, warp-shuffle based
__global__ void k_scan(int n) {
    __shared__ int wsum[32];
    __shared__ int carry;
    int tid = threadIdx.x, lane = tid & 31, w = tid >> 5;
    if (tid == 0) carry = 0;
    __syncthreads();
    int nchunks = (n + 1023) >> 10;
    for (int ch = 0; ch < nchunks; ++ch) {
        int i = ch * 1024 + tid;
        int v = (i < n) ? g_deg[i] : 0;
        int s = v;
        #pragma unroll
        for (int o = 1; o < 32; o <<= 1) {
            int t = __shfl_up_sync(0xffffffffu, s, o);
            if (lane >= o) s += t;
        }
        if (lane == 31) wsum[w] = s;
        __syncthreads();
        if (w == 0) {
            int ws = wsum[lane];
            #pragma unroll
            for (int o = 1; o < 32; o <<= 1) {
                int t = __shfl_up_sync(0xffffffffu, ws, o);
                if (lane >= o) ws += t;
            }
            wsum[lane] = ws;
        }
        __syncthreads();
        int incl = s + (w ? wsum[w - 1] : 0) + carry;
        if (i < n) g_offs[i + 1] = incl;
        __syncthreads();
        if (tid == 1023) carry = incl;
        __syncthreads();
    }
    if (threadIdx.x == 0) g_offs[0] = 0;
}

__global__ void k_fill(const int* __restrict__ ei, int E, int n) {
    int t = blockIdx.x * blockDim.x + threadIdx.x;
    if (t >= E + n) return;
    int s, d;
    if (t < E) { s = ei[t]; d = ei[E + t]; }
    else       { s = d = t - E; }
    if (s < 0 || s >= n || d < 0 || d >= n) return;
    int pos = g_offs[d] + atomicAdd(&g_cur[d], 1);
    g_srcs[pos] = s;
}

// -------------------------------------------- per-node attention projections
__global__ void k_nodep(const float* __restrict__ x_ext, int x_sel,
                        const float* __restrict__ u,
                        const float* __restrict__ c, int K, int n) {
    int warp = (blockIdx.x * blockDim.x + threadIdx.x) >> 5;
    int lane = threadIdx.x & 31;
    if (warp >= n) return;
    const float* x = x_sel ? g_h : x_ext;
    const float* xr = x + (size_t)warp * K;
    float a0 = 0.f, a1 = 0.f, a2 = 0.f, a3 = 0.f;
    for (int k = lane; k < K; k += 32) {
        float xv = xr[k];
        float4 uv = ((const float4*)u)[k];
        a0 += xv * uv.x; a1 += xv * uv.y; a2 += xv * uv.z; a3 += xv * uv.w;
    }
    #pragma unroll
    for (int off = 16; off; off >>= 1) {
        a0 += __shfl_down_sync(0xffffffffu, a0, off);
        a1 += __shfl_down_sync(0xffffffffu, a1, off);
        a2 += __shfl_down_sync(0xffffffffu, a2, off);
        a3 += __shfl_down_sync(0xffffffffu, a3, off);
    }
    if (lane == 0) {
        float4 ea, eb;
        ea.x = expf(a0 + c[0]); ea.y = expf(a1 + c[1]);
        ea.z = expf(a2 + c[2]); ea.w = expf(a3 + c[3]);
        eb.x = expf(-a0); eb.y = expf(-a1); eb.z = expf(-a2); eb.w = expf(-a3);
        ((float4*)g_ea)[warp] = ea;
        ((float4*)g_eb)[warp] = eb;
    }
}

// -------------------------------------------------------- bf16 split utils
__device__ __forceinline__ uint32_t pack_bf16(float lo_elem, float hi_elem) {
    uint32_t r;
    asm("cvt.rn.bf16x2.f32 %0, %1, %2;" : "=r"(r) : "f"(hi_elem), "f"(lo_elem));
    return r;
}
__device__ __forceinline__ void split_pair(float f0, float f1,
                                           uint32_t& hw, uint32_t& lw) {
    hw = pack_bf16(f0, f1);
    float h0 = __uint_as_float(hw << 16);
    float h1 = __uint_as_float(hw & 0xffff0000u);
    lw = pack_bf16(f0 - h0, f1 - h1);
}

// ------------------------------------------------ input-space aggregation
__device__ __forceinline__ float4 fma4(float4 a, float s, float4 v) {
    a.x += s * v.x; a.y += s * v.y; a.z += s * v.z; a.w += s * v.w; return a;
}
__device__ __forceinline__ void store_split4(uint32_t* dh, uint32_t* dl, float4 r) {
    uint32_t h0, l0, h1, l1;
    split_pair(r.x, r.y, h0, l0);
    split_pair(r.z, r.w, h1, l1);
    *(uint2*)dh = make_uint2(h0, h1);
    *(uint2*)dl = make_uint2(l0, l1);
}

template<int IN, int ZC>
__global__ void k_agg_in(const float* __restrict__ x_ext, int x_sel, int n) {
    constexpr int V = IN / 128;
    int warp = (blockIdx.x * blockDim.x + threadIdx.x) >> 5;
    int lane = threadIdx.x & 31;
    if (warp >= n) return;
    const float* x = x_sel ? g_h : x_ext;
    int i  = warp;
    int s0 = g_offs[i], s1 = g_offs[i + 1];
    float4 ebi = ((const float4*)g_eb)[i];

    float4 acc[4][V];
    #pragma unroll
    for (int h = 0; h < 4; h++)
        #pragma unroll
        for (int v = 0; v < V; v++) acc[h][v] = make_float4(0.f, 0.f, 0.f, 0.f);

    int j = (s0 < s1) ? g_srcs[s0] : 0;
    float4 a = ((const float4*)g_ea)[j];
    for (int e = s0; e < s1; ++e) {
        int jn = 0; float4 an = a;
        if (e + 1 < s1) {
            jn = g_srcs[e + 1];
            an = ((const float4*)g_ea)[jn];
        }
        float q0 = a.x * ebi.x, q1 = a.y * ebi.y, q2 = a.z * ebi.z, q3 = a.w * ebi.w;
        float rz = 1.0f / (q0 + q1 + q2 + q3);
        q0 *= rz; q1 *= rz; q2 *= rz; q3 *= rz;
        const float4* xj = (const float4*)(x + (size_t)j * IN);
        #pragma unroll
        for (int v = 0; v < V; v++) {
            float4 xv = xj[lane + 32 * v];
            acc[0][v] = fma4(acc[0][v], q0, xv);
            acc[1][v] = fma4(acc[1][v], q1, xv);
            acc[2][v] = fma4(acc[2][v], q2, xv);
            acc[3][v] = fma4(acc[3][v], q3, xv);
        }
        j = jn; a = an;
    }
    float inv = 1.0f / (float)(s1 - s0 > 0 ? s1 - s0 : 1);
    uint32_t* zh = g_yh + (size_t)i * 512;
    uint32_t* zl = g_yl + (size_t)i * 512;
    #pragma unroll
    for (int h = 0; h < 4; h++)
        #pragma unroll
        for (int v = 0; v < V; v++) {
            float4 r = acc[h][v];
            r.x *= inv; r.y *= inv; r.z *= inv; r.w *= inv;
            int wi = (h * IN) / 2 + 2 * (lane + 32 * v);
            store_split4(zh + wi, zl + wi, r);
        }
    if (ZC > 4 * IN) {
        const float4* xi = (const float4*)(x + (size_t)i * IN);
        #pragma unroll
        for (int v = 0; v < V; v++) {
            float4 r = xi[lane + 32 * v];
            int wi = 2 * IN + 2 * (lane + 32 * v);
            store_split4(zh + wi, zl + wi, r);
        }
    }
}

// ------------------------------- stacked weight builders + bf16 pre-split
__global__ void k_wsplit0(const float* __restrict__ W0,
                          const float* __restrict__ skipW0) {
    int t = blockIdx.x * blockDim.x + threadIdx.x;
    if (t >= 320 * 256) return;              // K=640 -> 320 pair rows
    int p = t >> 8, d = t & 255;
    float f[2];
    #pragma unroll
    for (int e = 0; e < 2; e++) {
        int r = 2 * p + e;
        if (r < 512) { int h = r >> 7, c = r & 127; f[e] = W0[c * 1024 + h * 256 + d]; }
        else         { int c = r - 512;             f[e] = skipW0[c * 256 + d]; }
    }
    uint32_t hw, lw;
    split_pair(f[0], f[1], hw, lw);
    g_wbh[t] = hw; g_wbl[t] = lw;
}
__global__ void k_wsplit1(const float* __restrict__ W1) {
    int t = blockIdx.x * blockDim.x + threadIdx.x;
    if (t >= 512 * 256) return;              // K=1024 -> 512 pair rows
    int p = t >> 8, d = t & 255;
    float f[2];
    #pragma unroll
    for (int e = 0; e < 2; e++) {
        int r = 2 * p + e;
        int h = r >> 8, c = r & 255;
        f[e] = W1[c * 1024 + h * 256 + d];
    }
    uint32_t hw, lw;
    split_pair(f[0], f[1], hw, lw);
    g_wbh[t] = hw; g_wbl[t] = lw;
}

// ----------------------------------------------------- bf16-split MMA GEMM
__device__ __forceinline__ void mma_bf16(float* c, const uint32_t* a, const uint32_t* b) {
    asm volatile(
        "mma.sync.aligned.m16n8k16.row.col.f32.bf16.bf16.f32 "
        "{%0,%1,%2,%3}, {%4,%5,%6,%7}, {%8,%9}, {%0,%1,%2,%3};"
        : "+f"(c[0]), "+f"(c[1]), "+f"(c[2]), "+f"(c[3])
        : "r"(a[0]), "r"(a[1]), "r"(a[2]), "r"(a[3]), "r"(b[0]), "r"(b[1]));
}
__device__ __forceinline__ void cp_async16(uint32_t smem_addr, const void* gptr) {
    asm volatile("cp.async.cg.shared.global [%0], [%1], 16;"
                 :: "r"(smem_addr), "l"(gptr));
}

// C = relu(A@B + b (+b2) (+g_h residual)).  A: g_yh/g_yl. B: g_wbh/g_wbl.
// Tile 64(M) x 128(N) x 32(K), 2-stage cp.async pipeline in dynamic smem.
// 256 threads, 8 warps (2m x 4n), warp 32x32. grid (2, ceil(M/64)), occ 3.
#define AW 20    // words per A row (16 data + 4 pad)
#define BW 136   // words per B pair-row (128 data + 8 pad); 136 % 32 == 8
#define ST_AH 0
#define ST_AL (64 * AW)
#define ST_BH (2 * 64 * AW)
#define ST_BL (2 * 64 * AW + 16 * BW)
#define STAGE_WORDS (2 * 64 * AW + 2 * 16 * BW)   // 6912 words = 27648 B
#define SMEM_BYTES (2 * STAGE_WORDS * 4)          // 55296 B

__global__ void __launch_bounds__(256, 3) k_mma(const float* __restrict__ b,
                                                const float* __restrict__ b2,
                                                int add_sel,
                                                float* __restrict__ out_ext, int out_sel,
                                                int M, int K) {
    extern __shared__ uint32_t dyn[];
    float* C = out_sel ? out_ext : g_h;

    int tid = threadIdx.x;
    int wid = tid >> 5, lane = tid & 31;
    int g   = lane >> 2;
    int tig = lane & 3;
    int warp_m = (wid >> 2) * 32;
    int warp_n = (wid & 3) * 32;
    int m0 = blockIdx.y * 64;
    int n0 = blockIdx.x * 128;

    float acc[2][4][4];
    #pragma unroll
    for (int i = 0; i < 2; i++)
        #pragma unroll
        for (int j = 0; j < 4; j++)
            #pragma unroll
            for (int q = 0; q < 4; q++) acc[i][j][q] = 0.f;

    // loader mappings
    int arow = tid >> 2;
    int aseg = (tid & 3) * 4;
    bool a_ok = (m0 + arow) < M;
    int bp = tid >> 5;
    int bn = lane * 4;

    // per-stage smem byte addresses for this thread's loader slots
    uint32_t base_s = (uint32_t)__cvta_generic_to_shared(dyn);
    uint32_t ah_s[2], al_s[2], bh0_s[2], bh1_s[2], bl0_s[2], bl1_s[2];
    #pragma unroll
    for (int st = 0; st < 2; st++) {
        uint32_t sb = base_s + st * (STAGE_WORDS * 4);
        ah_s[st]  = sb + (ST_AH + arow * AW + aseg) * 4;
        al_s[st]  = sb + (ST_AL + arow * AW + aseg) * 4;
        bh0_s[st] = sb + (ST_BH + bp * BW + bn) * 4;
        bh1_s[st] = sb + (ST_BH + (bp + 8) * BW + bn) * 4;
        bl0_s[st] = sb + (ST_BL + bp * BW + bn) * 4;
        bl1_s[st] = sb + (ST_BL + (bp + 8) * BW + bn) * 4;
    }

    int nsteps = K >> 5;

    // issue loads for a stage at k-step 'step'
    auto issue = [&](int st, int step) {
        int k0 = step << 5;
        int gp0 = k0 >> 1;
        cp_async16(bh0_s[st], &g_wbh[(gp0 + bp) * 256 + n0 + bn]);
        cp_async16(bh1_s[st], &g_wbh[(gp0 + bp + 8) * 256 + n0 + bn]);
        cp_async16(bl0_s[st], &g_wbl[(gp0 + bp) * 256 + n0 + bn]);
        cp_async16(bl1_s[st], &g_wbl[(gp0 + bp + 8) * 256 + n0 + bn]);
        if (a_ok) {
            size_t gw = (size_t)(m0 + arow) * 512 + gp0 + aseg;
            cp_async16(ah_s[st], &g_yh[gw]);
            cp_async16(al_s[st], &g_yl[gw]);
        } else {
            uint32_t* st_base = dyn + st * STAGE_WORDS;
            *(uint4*)&st_base[ST_AH + arow * AW + aseg] = make_uint4(0, 0, 0, 0);
            *(uint4*)&st_base[ST_AL + arow * AW + aseg] = make_uint4(0, 0, 0, 0);
        }
        asm volatile("cp.async.commit_group;");
    };

    issue(0, 0);
    for (int s = 0; s < nsteps; s++) {
        int cur = s & 1;
        if (s + 1 < nsteps) {
            issue(cur ^ 1, s + 1);
            asm volatile("cp.async.wait_group 1;");
        } else {
            asm volatile("cp.async.wait_group 0;");
        }
        __syncthreads();

        const uint32_t* Ah = dyn + cur * STAGE_WORDS + ST_AH;
        const uint32_t* Al = dyn + cur * STAGE_WORDS + ST_AL;
        const uint32_t* Bh = dyn + cur * STAGE_WORDS + ST_BH;
        const uint32_t* Bl = dyn + cur * STAGE_WORDS + ST_BL;

        #pragma unroll
        for (int kk2 = 0; kk2 < 2; kk2++) {       // two k16 steps
            int K0 = kk2 * 8;
            uint32_t ah[2][4], al[2][4];
            #pragma unroll
            for (int mt = 0; mt < 2; mt++) {
                int mr = warp_m + mt * 16 + g;
                ah[mt][0] = Ah[(mr)     * AW + K0 + tig];
                ah[mt][1] = Ah[(mr + 8) * AW + K0 + tig];
                ah[mt][2] = Ah[(mr)     * AW + K0 + 4 + tig];
                ah[mt][3] = Ah[(mr + 8) * AW + K0 + 4 + tig];
                al[mt][0] = Al[(mr)     * AW + K0 + tig];
                al[mt][1] = Al[(mr + 8) * AW + K0 + tig];
                al[mt][2] = Al[(mr)     * AW + K0 + 4 + tig];
                al[mt][3] = Al[(mr + 8) * AW + K0 + 4 + tig];
            }
            #pragma unroll
            for (int nt = 0; nt < 4; nt++) {
                int nc = warp_n + nt * 8 + g;
                uint32_t bh[2], bl[2];
                bh[0] = Bh[(K0 + tig)     * BW + nc];
                bh[1] = Bh[(K0 + 4 + tig) * BW + nc];
                bl[0] = Bl[(K0 + tig)     * BW + nc];
                bl[1] = Bl[(K0 + 4 + tig) * BW + nc];
                #pragma unroll
                for (int mt = 0; mt < 2; mt++) {
                    mma_bf16(acc[mt][nt], ah[mt], bl);
                    mma_bf16(acc[mt][nt], al[mt], bh);
                    mma_bf16(acc[mt][nt], ah[mt], bh);
                }
            }
        }
        __syncthreads();
    }

    // ---- fused epilogue: bias (+bias2) (+residual) + relu ----
    #pragma unroll
    for (int mt = 0; mt < 2; mt++) {
        int r = m0 + warp_m + mt * 16 + g;
        #pragma unroll
        for (int nt = 0; nt < 4; nt++) {
            int cc = n0 + warp_n + nt * 8 + tig * 2;
            float bb0 = b[cc], bb1 = b[cc + 1];
            if (b2) { bb0 += b2[cc]; bb1 += b2[cc + 1]; }
            if (r < M) {
                float v0 = acc[mt][nt][0] + bb0;
                float v1 = acc[mt][nt][1] + bb1;
                if (add_sel) {
                    v0 += g_h[(size_t)r * 256 + cc];
                    v1 += g_h[(size_t)r * 256 + cc + 1];
                }
                C[(size_t)r * 256 + cc]     = fmaxf(v0, 0.f);
                C[(size_t)r * 256 + cc + 1] = fmaxf(v1, 0.f);
            }
            if (r + 8 < M) {
                float v2 = acc[mt][nt][2] + bb0;
                float v3 = acc[mt][nt][3] + bb1;
                if (add_sel) {
                    v2 += g_h[(size_t)(r + 8) * 256 + cc];
                    v3 += g_h[(size_t)(r + 8) * 256 + cc + 1];
                }
                C[(size_t)(r + 8) * 256 + cc]     = fmaxf(v2, 0.f);
                C[(size_t)(r + 8) * 256 + cc + 1] = fmaxf(v3, 0.f);
            }
        }
    }
}

// -------------------------------------------------- edge_index passthrough
__global__ void k_copy_edges_f32(const int* __restrict__ ei,
                                 float* __restrict__ out, int n) {
    int t = blockIdx.x * blockDim.x + threadIdx.x;
    if (t < n) out[t] = (float)ei[t];
}

// ---------------------------------------------------------------- launcher
extern "C" void kernel_launch(void* const* d_in, const int* in_sizes, int n_in,
                              void* d_out, int out_size) {
    const float* x      = (const float*)d_in[0];
    const int*   ei     = (const int*)d_in[1];     // int32 (JAX x64 disabled)
    const float* W0     = (const float*)d_in[2];
    const float* u0     = (const float*)d_in[3];
    const float* c0     = (const float*)d_in[4];
    const float* b0     = (const float*)d_in[5];
    const float* skipW0 = (const float*)d_in[6];
    const float* skipb0 = (const float*)d_in[7];
    const float* W1     = (const float*)d_in[8];
    const float* u1     = (const float*)d_in[9];
    const float* c1     = (const float*)d_in[10];
    const float* b1     = (const float*)d_in[11];

    int N = in_sizes[0] / 128;
    int E = in_sizes[1] / 2;
    if (N > MAXN || E > MAXE) return;

    float* out = (float*)d_out;

    // allow >48KB dynamic smem for the pipelined GEMM (attribute set is
    // not stream-ordered -> graph-capture safe; deterministic every call)
    cudaFuncSetAttribute(k_mma, cudaFuncAttributeMaxDynamicSharedMemorySize,
                         SMEM_BYTES);

    // CSR build
    k_init<<<(N + 255) / 256, 256>>>(N);
    k_hist<<<(E + 255) / 256, 256>>>(ei, E, N);
    k_scan<<<1, 1024>>>(N);
    k_fill<<<(E + N + 255) / 256, 256>>>(ei, E, N);

    // ---- conv0 ----
    k_wsplit0<<<(320 * 256 + 255) / 256, 256>>>(W0, skipW0);
    k_nodep<<<(N * 32 + 255) / 256, 256>>>(x, 0, u0, c0, 128, N);
    k_agg_in<128, 640><<<(N * 32 + 255) / 256, 256>>>(x, 0, N);
    {   // g_h = relu(z[:,0:640] @ Wstack0 + b0 + skipb0)
        dim3 grid(2, (N + 63) / 64);
        k_mma<<<grid, 256, SMEM_BYTES>>>(b0, skipb0, 0, (float*)nullptr, 0, N, 640);
    }

    // ---- conv1 ----
    k_wsplit1<<<(512 * 256 + 255) / 256, 256>>>(W1);
    k_nodep<<<(N * 32 + 255) / 256, 256>>>((const float*)nullptr, 1, u1, c1, 256, N);
    k_agg_in<256, 1024><<<(N * 32 + 255) / 256, 256>>>((const float*)nullptr, 1, N);
    {   // out = relu(z @ Wstack1 + b1 + g_h)
        dim3 grid(2, (N + 63) / 64);
        k_mma<<<grid, 256, SMEM_BYTES>>>(b1, (const float*)nullptr, 1, out, 1, N, 1024);
    }

    // edge_index passthrough
    long long hElems = (long long)N * 256;
    long long rem = (long long)out_size - hElems;
    if (rem >= 2LL * E) {
        k_copy_edges_f32<<<(2 * E + 255) / 256, 256>>>(ei, out + hElems, 2 * E);
    }
}

// round 12
// speedup vs baseline: 1.3536x; 1.0312x over previous
#include <cuda_runtime.h>
#include <cstdint>

// ---------------------------------------------------------------------------
// FeaStEncoderBlock, input-space aggregation + bf16-split tensor-core GEMM.
// Round 12 (GEMM frozen at HMMA roofline; tail optimizations):
//   - k_agg_in: x-row register prefetch (1-iteration lookahead on the gather)
//   - k_scan: 4 elements/thread (5 barrier rounds instead of 20)
//   - fused k_init+edge-copy; fused wsplit0+wsplit1 (separate W buffers)
// ---------------------------------------------------------------------------

#define MAXN 20000
#define MAXE 320000

__device__ __align__(16) uint32_t g_yh[(size_t)MAXN * 512];   // z hi pair-words
__device__ __align__(16) uint32_t g_yl[(size_t)MAXN * 512];   // z lo pair-words
__device__ __align__(16) float    g_h[(size_t)MAXN * 256];    // hidden h
__device__ __align__(16) uint32_t g_wbh0[320 * 256];          // conv0 W hi
__device__ __align__(16) uint32_t g_wbl0[320 * 256];          // conv0 W lo
__device__ __align__(16) uint32_t g_wbh1[512 * 256];          // conv1 W hi
__device__ __align__(16) uint32_t g_wbl1[512 * 256];          // conv1 W lo
__device__ __align__(16) float    g_ea[MAXN * 4];
__device__ __align__(16) float    g_eb[MAXN * 4];
__device__ int g_deg[MAXN];
__device__ int g_cur[MAXN];
__device__ int g_offs[MAXN + 1];
__device__ int g_srcs[MAXN + MAXE];

// --------------------------------------- CSR init + edge passthrough (fused)
__global__ void k_init_edges(const int* __restrict__ ei,
                             float* __restrict__ out, int n, int twoE,
                             int do_edges) {
    int t = blockIdx.x * blockDim.x + threadIdx.x;
    if (t < n) { g_deg[t] = 1; g_cur[t] = 0; }
    if (do_edges && t < twoE) out[t] = (float)ei[t];
}

__global__ void k_hist(const int* __restrict__ ei, int E, int n) {
    int t = blockIdx.x * blockDim.x + threadIdx.x;
    if (t < E) {
        int d = ei[E + t];
        if (d >= 0 && d < n) atomicAdd(&g_deg[d], 1);
    }
}

// single-block exclusive scan, 4 elements/thread, warp-shuffle based
__global__ void k_scan(int n) {
    __shared__ int wsum[32];
    __shared__ int carry;
    int tid = threadIdx.x, lane = tid & 31, w = tid >> 5;
    if (tid == 0) carry = 0;
    __syncthreads();
    int nch = (n + 4095) >> 12;
    for (int ch = 0; ch < nch; ++ch) {
        int i = ch * 4096 + tid * 4;
        int v0 = (i     < n) ? g_deg[i]     : 0;
        int v1 = (i + 1 < n) ? g_deg[i + 1] : 0;
        int v2 = (i + 2 < n) ? g_deg[i + 2] : 0;
        int v3 = (i + 3 < n) ? g_deg[i + 3] : 0;
        int p0 = v0, p1 = p0 + v1, p2 = p1 + v2, p3 = p2 + v3;
        int s = p3;
        #pragma unroll
        for (int o = 1; o < 32; o <<= 1) {
            int t2 = __shfl_up_sync(0xffffffffu, s, o);
            if (lane >= o) s += t2;
        }
        if (lane == 31) wsum[w] = s;
        __syncthreads();
        if (w == 0) {
            int ws = wsum[lane];
            #pragma unroll
            for (int o = 1; o < 32; o <<= 1) {
                int t2 = __shfl_up_sync(0xffffffffu, ws, o);
                if (lane >= o) ws += t2;
            }
            wsum[lane] = ws;
        }
        __syncthreads();
        int base = carry + (w ? wsum[w - 1] : 0) + (s - p3);
        if (i     < n) g_offs[i + 1] = base + p0;
        if (i + 1 < n) g_offs[i + 2] = base + p1;
        if (i + 2 < n) g_offs[i + 3] = base + p2;
        if (i + 3 < n) g_offs[i + 4] = base + p3;
        __syncthreads();
        if (tid == 1023) carry = base + p3;
        __syncthreads();
    }
    if (threadIdx.x == 0) g_offs[0] = 0;
}

__global__ void k_fill(const int* __restrict__ ei, int E, int n) {
    int t = blockIdx.x * blockDim.x + threadIdx.x;
    if (t >= E + n) return;
    int s, d;
    if (t < E) { s = ei[t]; d = ei[E + t]; }
    else       { s = d = t - E; }
    if (s < 0 || s >= n || d < 0 || d >= n) return;
    int pos = g_offs[d] + atomicAdd(&g_cur[d], 1);
    g_srcs[pos] = s;
}

// -------------------------------------------- per-node attention projections
__global__ void k_nodep(const float* __restrict__ x_ext, int x_sel,
                        const float* __restrict__ u,
                        const float* __restrict__ c, int K, int n) {
    int warp = (blockIdx.x * blockDim.x + threadIdx.x) >> 5;
    int lane = threadIdx.x & 31;
    if (warp >= n) return;
    const float* x = x_sel ? g_h : x_ext;
    const float* xr = x + (size_t)warp * K;
    float a0 = 0.f, a1 = 0.f, a2 = 0.f, a3 = 0.f;
    for (int k = lane; k < K; k += 32) {
        float xv = xr[k];
        float4 uv = ((const float4*)u)[k];
        a0 += xv * uv.x; a1 += xv * uv.y; a2 += xv * uv.z; a3 += xv * uv.w;
    }
    #pragma unroll
    for (int off = 16; off; off >>= 1) {
        a0 += __shfl_down_sync(0xffffffffu, a0, off);
        a1 += __shfl_down_sync(0xffffffffu, a1, off);
        a2 += __shfl_down_sync(0xffffffffu, a2, off);
        a3 += __shfl_down_sync(0xffffffffu, a3, off);
    }
    if (lane == 0) {
        float4 ea, eb;
        ea.x = expf(a0 + c[0]); ea.y = expf(a1 + c[1]);
        ea.z = expf(a2 + c[2]); ea.w = expf(a3 + c[3]);
        eb.x = expf(-a0); eb.y = expf(-a1); eb.z = expf(-a2); eb.w = expf(-a3);
        ((float4*)g_ea)[warp] = ea;
        ((float4*)g_eb)[warp] = eb;
    }
}

// -------------------------------------------------------- bf16 split utils
__device__ __forceinline__ uint32_t pack_bf16(float lo_elem, float hi_elem) {
    uint32_t r;
    asm("cvt.rn.bf16x2.f32 %0, %1, %2;" : "=r"(r) : "f"(hi_elem), "f"(lo_elem));
    return r;
}
__device__ __forceinline__ void split_pair(float f0, float f1,
                                           uint32_t& hw, uint32_t& lw) {
    hw = pack_bf16(f0, f1);
    float h0 = __uint_as_float(hw << 16);
    float h1 = __uint_as_float(hw & 0xffff0000u);
    lw = pack_bf16(f0 - h0, f1 - h1);
}

// ------------------------------------------------ input-space aggregation
__device__ __forceinline__ float4 fma4(float4 a, float s, float4 v) {
    a.x += s * v.x; a.y += s * v.y; a.z += s * v.z; a.w += s * v.w; return a;
}
__device__ __forceinline__ void store_split4(uint32_t* dh, uint32_t* dl, float4 r) {
    uint32_t h0, l0, h1, l1;
    split_pair(r.x, r.y, h0, l0);
    split_pair(r.z, r.w, h1, l1);
    *(uint2*)dh = make_uint2(h0, h1);
    *(uint2*)dl = make_uint2(l0, l1);
}

template<int IN, int ZC>
__global__ void k_agg_in(const float* __restrict__ x_ext, int x_sel, int n) {
    constexpr int V = IN / 128;
    int warp = (blockIdx.x * blockDim.x + threadIdx.x) >> 5;
    int lane = threadIdx.x & 31;
    if (warp >= n) return;
    const float* x = x_sel ? g_h : x_ext;
    int i  = warp;
    int s0 = g_offs[i], s1 = g_offs[i + 1];
    float4 ebi = ((const float4*)g_eb)[i];

    float4 acc[4][V];
    #pragma unroll
    for (int h = 0; h < 4; h++)
        #pragma unroll
        for (int v = 0; v < V; v++) acc[h][v] = make_float4(0.f, 0.f, 0.f, 0.f);

    // software-pipelined edge loop: prefetch next index + ea + x row
    int j = (s0 < s1) ? g_srcs[s0] : 0;
    float4 a = ((const float4*)g_ea)[j];
    float4 xv[V];
    {
        const float4* xj = (const float4*)(x + (size_t)j * IN);
        #pragma unroll
        for (int v = 0; v < V; v++) xv[v] = (s0 < s1) ? xj[lane + 32 * v]
                                                      : make_float4(0.f,0.f,0.f,0.f);
    }
    for (int e = s0; e < s1; ++e) {
        int jn = 0; float4 an = a;
        float4 xvn[V];
        #pragma unroll
        for (int v = 0; v < V; v++) xvn[v] = xv[v];
        if (e + 1 < s1) {
            jn = g_srcs[e + 1];
            an = ((const float4*)g_ea)[jn];
            const float4* xjn = (const float4*)(x + (size_t)jn * IN);
            #pragma unroll
            for (int v = 0; v < V; v++) xvn[v] = xjn[lane + 32 * v];
        }
        float q0 = a.x * ebi.x, q1 = a.y * ebi.y, q2 = a.z * ebi.z, q3 = a.w * ebi.w;
        float rz = 1.0f / (q0 + q1 + q2 + q3);
        q0 *= rz; q1 *= rz; q2 *= rz; q3 *= rz;
        #pragma unroll
        for (int v = 0; v < V; v++) {
            acc[0][v] = fma4(acc[0][v], q0, xv[v]);
            acc[1][v] = fma4(acc[1][v], q1, xv[v]);
            acc[2][v] = fma4(acc[2][v], q2, xv[v]);
            acc[3][v] = fma4(acc[3][v], q3, xv[v]);
        }
        j = jn; a = an;
        #pragma unroll
        for (int v = 0; v < V; v++) xv[v] = xvn[v];
    }
    float inv = 1.0f / (float)(s1 - s0 > 0 ? s1 - s0 : 1);
    uint32_t* zh = g_yh + (size_t)i * 512;
    uint32_t* zl = g_yl + (size_t)i * 512;
    #pragma unroll
    for (int h = 0; h < 4; h++)
        #pragma unroll
        for (int v = 0; v < V; v++) {
            float4 r = acc[h][v];
            r.x *= inv; r.y *= inv; r.z *= inv; r.w *= inv;
            int wi = (h * IN) / 2 + 2 * (lane + 32 * v);
            store_split4(zh + wi, zl + wi, r);
        }
    if (ZC > 4 * IN) {
        const float4* xi = (const float4*)(x + (size_t)i * IN);
        #pragma unroll
        for (int v = 0; v < V; v++) {
            float4 r = xi[lane + 32 * v];
            int wi = 2 * IN + 2 * (lane + 32 * v);
            store_split4(zh + wi, zl + wi, r);
        }
    }
}

// ------------------------- fused stacked weight builder (both convs at once)
// conv0: 320 pair-rows (K=640: 512 W0-stacked + 128 skipW0), conv1: 512 rows.
__global__ void k_wsplit(const float* __restrict__ W0,
                         const float* __restrict__ skipW0,
                         const float* __restrict__ W1) {
    int t = blockIdx.x * blockDim.x + threadIdx.x;
    if (t < 320 * 256) {
        int p = t >> 8, d = t & 255;
        float f[2];
        #pragma unroll
        for (int e = 0; e < 2; e++) {
            int r = 2 * p + e;
            if (r < 512) { int h = r >> 7, c = r & 127; f[e] = W0[c * 1024 + h * 256 + d]; }
            else         { int c = r - 512;             f[e] = skipW0[c * 256 + d]; }
        }
        uint32_t hw, lw;
        split_pair(f[0], f[1], hw, lw);
        g_wbh0[t] = hw; g_wbl0[t] = lw;
    }
    int t1 = t - 320 * 256;
    if (t1 >= 0 && t1 < 512 * 256) {
        int p = t1 >> 8, d = t1 & 255;
        float f[2];
        #pragma unroll
        for (int e = 0; e < 2; e++) {
            int r = 2 * p + e;
            int h = r >> 8, c = r & 255;
            f[e] = W1[c * 1024 + h * 256 + d];
        }
        uint32_t hw, lw;
        split_pair(f[0], f[1], hw, lw);
        g_wbh1[t1] = hw; g_wbl1[t1] = lw;
    }
}

// ----------------------------------------------------- bf16-split MMA GEMM
__device__ __forceinline__ void mma_bf16(float* c, const uint32_t* a, const uint32_t* b) {
    asm volatile(
        "mma.sync.aligned.m16n8k16.row.col.f32.bf16.bf16.f32 "
        "{%0,%1,%2,%3}, {%4,%5,%6,%7}, {%8,%9}, {%0,%1,%2,%3};"
        : "+f"(c[0]), "+f"(c[1]), "+f"(c[2]), "+f"(c[3])
        : "r"(a[0]), "r"(a[1]), "r"(a[2]), "r"(a[3]), "r"(b[0]), "r"(b[1]));
}
__device__ __forceinline__ void cp_async16(uint32_t smem_addr, const void* gptr) {
    asm volatile("cp.async.cg.shared.global [%0], [%1], 16;"
                 :: "r"(smem_addr), "l"(gptr));
}

// C = relu(A@B + b (+b2) (+g_h residual)).  A: g_yh/g_yl. B: g_wb*{0,1}.
// Tile 64(M) x 128(N) x 32(K), 2-stage cp.async pipeline in dynamic smem.
// 256 threads, 8 warps (2m x 4n), warp 32x32. grid (2, ceil(M/64)), occ 3.
#define AW 20
#define BW 136
#define ST_AH 0
#define ST_AL (64 * AW)
#define ST_BH (2 * 64 * AW)
#define ST_BL (2 * 64 * AW + 16 * BW)
#define STAGE_WORDS (2 * 64 * AW + 2 * 16 * BW)   // 6912 words = 27648 B
#define SMEM_BYTES (2 * STAGE_WORDS * 4)          // 55296 B

__global__ void __launch_bounds__(256, 3) k_mma(const float* __restrict__ b,
                                                const float* __restrict__ b2,
                                                int add_sel, int wsel,
                                                float* __restrict__ out_ext, int out_sel,
                                                int M, int K) {
    extern __shared__ uint32_t dyn[];
    float* C = out_sel ? out_ext : g_h;
    const uint32_t* WH = wsel ? g_wbh1 : g_wbh0;
    const uint32_t* WL = wsel ? g_wbl1 : g_wbl0;

    int tid = threadIdx.x;
    int wid = tid >> 5, lane = tid & 31;
    int g   = lane >> 2;
    int tig = lane & 3;
    int warp_m = (wid >> 2) * 32;
    int warp_n = (wid & 3) * 32;
    int m0 = blockIdx.y * 64;
    int n0 = blockIdx.x * 128;

    float acc[2][4][4];
    #pragma unroll
    for (int i = 0; i < 2; i++)
        #pragma unroll
        for (int j = 0; j < 4; j++)
            #pragma unroll
            for (int q = 0; q < 4; q++) acc[i][j][q] = 0.f;

    int arow = tid >> 2;
    int aseg = (tid & 3) * 4;
    bool a_ok = (m0 + arow) < M;
    int bp = tid >> 5;
    int bn = lane * 4;

    uint32_t base_s = (uint32_t)__cvta_generic_to_shared(dyn);
    uint32_t ah_s[2], al_s[2], bh0_s[2], bh1_s[2], bl0_s[2], bl1_s[2];
    #pragma unroll
    for (int st = 0; st < 2; st++) {
        uint32_t sb = base_s + st * (STAGE_WORDS * 4);
        ah_s[st]  = sb + (ST_AH + arow * AW + aseg) * 4;
        al_s[st]  = sb + (ST_AL + arow * AW + aseg) * 4;
        bh0_s[st] = sb + (ST_BH + bp * BW + bn) * 4;
        bh1_s[st] = sb + (ST_BH + (bp + 8) * BW + bn) * 4;
        bl0_s[st] = sb + (ST_BL + bp * BW + bn) * 4;
        bl1_s[st] = sb + (ST_BL + (bp + 8) * BW + bn) * 4;
    }

    int nsteps = K >> 5;

    auto issue = [&](int st, int step) {
        int k0 = step << 5;
        int gp0 = k0 >> 1;
        cp_async16(bh0_s[st], &WH[(gp0 + bp) * 256 + n0 + bn]);
        cp_async16(bh1_s[st], &WH[(gp0 + bp + 8) * 256 + n0 + bn]);
        cp_async16(bl0_s[st], &WL[(gp0 + bp) * 256 + n0 + bn]);
        cp_async16(bl1_s[st], &WL[(gp0 + bp + 8) * 256 + n0 + bn]);
        if (a_ok) {
            size_t gw = (size_t)(m0 + arow) * 512 + gp0 + aseg;
            cp_async16(ah_s[st], &g_yh[gw]);
            cp_async16(al_s[st], &g_yl[gw]);
        } else {
            uint32_t* st_base = dyn + st * STAGE_WORDS;
            *(uint4*)&st_base[ST_AH + arow * AW + aseg] = make_uint4(0, 0, 0, 0);
            *(uint4*)&st_base[ST_AL + arow * AW + aseg] = make_uint4(0, 0, 0, 0);
        }
        asm volatile("cp.async.commit_group;");
    };

    issue(0, 0);
    for (int s = 0; s < nsteps; s++) {
        int cur = s & 1;
        if (s + 1 < nsteps) {
            issue(cur ^ 1, s + 1);
            asm volatile("cp.async.wait_group 1;");
        } else {
            asm volatile("cp.async.wait_group 0;");
        }
        __syncthreads();

        const uint32_t* Ah = dyn + cur * STAGE_WORDS + ST_AH;
        const uint32_t* Al = dyn + cur * STAGE_WORDS + ST_AL;
        const uint32_t* Bh = dyn + cur * STAGE_WORDS + ST_BH;
        const uint32_t* Bl = dyn + cur * STAGE_WORDS + ST_BL;

        #pragma unroll
        for (int kk2 = 0; kk2 < 2; kk2++) {
            int K0 = kk2 * 8;
            uint32_t ah[2][4], al[2][4];
            #pragma unroll
            for (int mt = 0; mt < 2; mt++) {
                int mr = warp_m + mt * 16 + g;
                ah[mt][0] = Ah[(mr)     * AW + K0 + tig];
                ah[mt][1] = Ah[(mr + 8) * AW + K0 + tig];
                ah[mt][2] = Ah[(mr)     * AW + K0 + 4 + tig];
                ah[mt][3] = Ah[(mr + 8) * AW + K0 + 4 + tig];
                al[mt][0] = Al[(mr)     * AW + K0 + tig];
                al[mt][1] = Al[(mr + 8) * AW + K0 + tig];
                al[mt][2] = Al[(mr)     * AW + K0 + 4 + tig];
                al[mt][3] = Al[(mr + 8) * AW + K0 + 4 + tig];
            }
            #pragma unroll
            for (int nt = 0; nt < 4; nt++) {
                int nc = warp_n + nt * 8 + g;
                uint32_t bh[2], bl[2];
                bh[0] = Bh[(K0 + tig)     * BW + nc];
                bh[1] = Bh[(K0 + 4 + tig) * BW + nc];
                bl[0] = Bl[(K0 + tig)     * BW + nc];
                bl[1] = Bl[(K0 + 4 + tig) * BW + nc];
                #pragma unroll
                for (int mt = 0; mt < 2; mt++) {
                    mma_bf16(acc[mt][nt], ah[mt], bl);
                    mma_bf16(acc[mt][nt], al[mt], bh);
                    mma_bf16(acc[mt][nt], ah[mt], bh);
                }
            }
        }
        __syncthreads();
    }

    // ---- fused epilogue: bias (+bias2) (+residual) + relu ----
    #pragma unroll
    for (int mt = 0; mt < 2; mt++) {
        int r = m0 + warp_m + mt * 16 + g;
        #pragma unroll
        for (int nt = 0; nt < 4; nt++) {
            int cc = n0 + warp_n + nt * 8 + tig * 2;
            float bb0 = b[cc], bb1 = b[cc + 1];
            if (b2) { bb0 += b2[cc]; bb1 += b2[cc + 1]; }
            if (r < M) {
                float v0 = acc[mt][nt][0] + bb0;
                float v1 = acc[mt][nt][1] + bb1;
                if (add_sel) {
                    v0 += g_h[(size_t)r * 256 + cc];
                    v1 += g_h[(size_t)r * 256 + cc + 1];
                }
                C[(size_t)r * 256 + cc]     = fmaxf(v0, 0.f);
                C[(size_t)r * 256 + cc + 1] = fmaxf(v1, 0.f);
            }
            if (r + 8 < M) {
                float v2 = acc[mt][nt][2] + bb0;
                float v3 = acc[mt][nt][3] + bb1;
                if (add_sel) {
                    v2 += g_h[(size_t)(r + 8) * 256 + cc];
                    v3 += g_h[(size_t)(r + 8) * 256 + cc + 1];
                }
                C[(size_t)(r + 8) * 256 + cc]     = fmaxf(v2, 0.f);
                C[(size_t)(r + 8) * 256 + cc + 1] = fmaxf(v3, 0.f);
            }
        }
    }
}

// ---------------------------------------------------------------- launcher
extern "C" void kernel_launch(void* const* d_in, const int* in_sizes, int n_in,
                              void* d_out, int out_size) {
    const float* x      = (const float*)d_in[0];
    const int*   ei     = (const int*)d_in[1];     // int32 (JAX x64 disabled)
    const float* W0     = (const float*)d_in[2];
    const float* u0     = (const float*)d_in[3];
    const float* c0     = (const float*)d_in[4];
    const float* b0     = (const float*)d_in[5];
    const float* skipW0 = (const float*)d_in[6];
    const float* skipb0 = (const float*)d_in[7];
    const float* W1     = (const float*)d_in[8];
    const float* u1     = (const float*)d_in[9];
    const float* c1     = (const float*)d_in[10];
    const float* b1     = (const float*)d_in[11];

    int N = in_sizes[0] / 128;
    int E = in_sizes[1] / 2;
    if (N > MAXN || E > MAXE) return;

    float* out = (float*)d_out;

    cudaFuncSetAttribute(k_mma, cudaFuncAttributeMaxDynamicSharedMemorySize,
                         SMEM_BYTES);

    // CSR init + edge passthrough (fused) + weight pre-split (fused)
    long long hElems = (long long)N * 256;
    int do_edges = ((long long)out_size - hElems >= 2LL * E) ? 1 : 0;
    int initN = (2 * E > N) ? 2 * E : N;
    k_init_edges<<<(initN + 255) / 256, 256>>>(ei, out + hElems, N, 2 * E, do_edges);
    k_wsplit<<<((320 + 512) * 256 + 255) / 256, 256>>>(W0, skipW0, W1);

    // CSR build
    k_hist<<<(E + 255) / 256, 256>>>(ei, E, N);
    k_scan<<<1, 1024>>>(N);
    k_fill<<<(E + N + 255) / 256, 256>>>(ei, E, N);

    // ---- conv0 ----
    k_nodep<<<(N * 32 + 255) / 256, 256>>>(x, 0, u0, c0, 128, N);
    k_agg_in<128, 640><<<(N * 32 + 255) / 256, 256>>>(x, 0, N);
    {   // g_h = relu(z[:,0:640] @ Wstack0 + b0 + skipb0)
        dim3 grid(2, (N + 63) / 64);
        k_mma<<<grid, 256, SMEM_BYTES>>>(b0, skipb0, 0, 0, (float*)nullptr, 0, N, 640);
    }

    // ---- conv1 ----
    k_nodep<<<(N * 32 + 255) / 256, 256>>>((const float*)nullptr, 1, u1, c1, 256, N);
    k_agg_in<256, 1024><<<(N * 32 + 255) / 256, 256>>>((const float*)nullptr, 1, N);
    {   // out = relu(z @ Wstack1 + b1 + g_h)
        dim3 grid(2, (N + 63) / 64);
        k_mma<<<grid, 256, SMEM_BYTES>>>(b1, (const float*)nullptr, 1, 1, out, 1, N, 1024);
    }
}